// round 9
// baseline (speedup 1.0000x reference)
#include <cuda_runtime.h>
#include <cuda_bf16.h>
#include <math_constants.h>
#include <cstdint>

#define BATCH 4
#define SEQ   2048
#define DIM   1024
#define K3P   (3 * DIM)   // 3072
#define K3S   (3 * SEQ)   // 6144

#define BM 128
#define BN 128
#define BK 64
#define THREADS 128        // scores/pv: 4 warps, warp tile 64x64
#define STAGES 3
#define A_STAGE_BYTES 18432u
#define STAGE_BYTES   36864u
#define SMEM_TOTAL (STAGES * STAGE_BYTES)   // 110592

// qkv int8 kernel smem: 3 stages x 4 planes x (128 rows x 80B)
#define PB  10240u
#define STB 40960u
#define QSM (3u * STB)     // 122880

// ---------------- scratch ----------------
__device__ signed char  g_x8 [2L * BATCH * SEQ * DIM];     // x int8 slices (plane0, plane1)
__device__ signed char  g_wq8[2L * DIM * DIM];
__device__ signed char  g_wk8[2L * DIM * DIM];
__device__ signed char  g_wv8[2L * DIM * DIM];
__device__ __nv_bfloat16 g_Q2 [(long)BATCH * SEQ * K3P];   // Q split A-layout (hi,lo,hi)
__device__ __nv_bfloat16 g_K2 [(long)BATCH * SEQ * K3P];   // K split B-layout (hi,hi,lo)
__device__ __nv_bfloat16 g_V2 [(long)BATCH * K3S * DIM];   // V split rows
__device__ float         g_S  [(long)BATCH * SEQ * SEQ];
__device__ __nv_bfloat16 g_P2 [(long)BATCH * SEQ * K3S];   // P split A-layout

// ---------------- asm helpers ----------------
__device__ __forceinline__ uint32_t smem_u32(const void* p) {
    uint32_t a;
    asm("{ .reg .u64 t; cvta.to.shared.u64 t, %1; cvt.u32.u64 %0, t; }" : "=r"(a) : "l"(p));
    return a;
}
#define LDMX4(r0,r1,r2,r3,addr) \
    asm volatile("ldmatrix.sync.aligned.m8n8.x4.shared.b16 {%0,%1,%2,%3}, [%4];" \
                 : "=r"(r0),"=r"(r1),"=r"(r2),"=r"(r3) : "r"(addr))
#define LDMX4T(r0,r1,r2,r3,addr) \
    asm volatile("ldmatrix.sync.aligned.m8n8.x4.trans.shared.b16 {%0,%1,%2,%3}, [%4];" \
                 : "=r"(r0),"=r"(r1),"=r"(r2),"=r"(r3) : "r"(addr))
#define MMA(c,a,b0,b1) \
    asm volatile("mma.sync.aligned.m16n8k16.row.col.f32.bf16.bf16.f32 " \
                 "{%0,%1,%2,%3}, {%4,%5,%6,%7}, {%8,%9}, {%0,%1,%2,%3};" \
                 : "+f"((c)[0]),"+f"((c)[1]),"+f"((c)[2]),"+f"((c)[3]) \
                 : "r"((a)[0]),"r"((a)[1]),"r"((a)[2]),"r"((a)[3]),"r"(b0),"r"(b1))
#define IMMA(c,a,b0,b1) \
    asm volatile("mma.sync.aligned.m16n8k32.row.col.s32.s8.s8.s32 " \
                 "{%0,%1,%2,%3}, {%4,%5,%6,%7}, {%8,%9}, {%0,%1,%2,%3};" \
                 : "+r"((c)[0]),"+r"((c)[1]),"+r"((c)[2]),"+r"((c)[3]) \
                 : "r"((a)[0]),"r"((a)[1]),"r"((a)[2]),"r"((a)[3]),"r"(b0),"r"(b1))
#define CPASYNC(s,g) \
    asm volatile("cp.async.cg.shared.global [%0], [%1], 16;" :: "r"(s),"l"(g))
#define CP_COMMIT() asm volatile("cp.async.commit_group;" ::: "memory")
#define CP_WAIT(N)  asm volatile("cp.async.wait_group %0;" :: "n"(N) : "memory")

__device__ __forceinline__ void split_us(float v, unsigned short& h, unsigned short& l) {
    __nv_bfloat16 hb = __float2bfloat16(v);
    __nv_bfloat16 lb = __float2bfloat16(v - __bfloat162float(hb));
    h = __bfloat16_as_ushort(hb);
    l = __bfloat16_as_ushort(lb);
}

__device__ __forceinline__ void store_split_pair(uint32_t* p, float v0, float v1, int lay) {
    unsigned short h0, l0, h1, l1;
    split_us(v0, h0, l0);
    split_us(v1, h1, l1);
    if (lay == 1) {        // A-layout hi,lo,hi
        p[0] = (uint32_t)h0 | ((uint32_t)l0 << 16);
        p[1] = (uint32_t)h0 | ((uint32_t)h1 << 16);
        p[2] = (uint32_t)l1 | ((uint32_t)h1 << 16);
    } else {               // B-layout hi,hi,lo
        p[0] = (uint32_t)h0 | ((uint32_t)h0 << 16);
        p[1] = (uint32_t)l0 | ((uint32_t)h1 << 16);
        p[2] = (uint32_t)h1 | ((uint32_t)l1 << 16);
    }
}

// ---------------- int8 quantization: v = S*(128*p0 + p1)/16256 ----------------
__global__ void quant8(const float* __restrict__ in, signed char* __restrict__ p0,
                       signed char* __restrict__ p1, long n, float inv_scale) {
    long i = (long)blockIdx.x * blockDim.x + threadIdx.x;
    if (i >= n) return;
    float t = in[i] * inv_scale;
    t = fminf(1.f, fmaxf(-1.f, t));
    float a  = rintf(t * 127.f);
    float a1 = rintf((t * 127.f - a) * 128.f);
    p0[i] = (signed char)(int)a;
    p1[i] = (signed char)(int)a1;
}

// ================= int8 QKV projection (3 slice-product passes) =================
// planes in smem per stage: 0=A0, 1=A1, 2=B0, 3=B1; 128 rows x 64B (80B stride)
#define QK_LDA(dst, pl, ks)                                                             \
    { _Pragma("unroll")                                                                 \
      for (int mi = 0; mi < 2; mi++)                                                    \
          LDMX4(dst[mi][0], dst[mi][1], dst[mi][2], dst[mi][3],                         \
                sb_ + (pl) * PB + (uint32_t)((wm * 32 + mi * 16 + l15) * 80 + lh * 16 + (ks) * 32)); }

#define QK_LDB(dst, pl, ks)                                                             \
    { _Pragma("unroll")                                                                 \
      for (int j2 = 0; j2 < 4; j2++) {                                                  \
          uint32_t r0, r1, r2, r3;                                                      \
          LDMX4(r0, r1, r2, r3,                                                         \
                sb_ + (pl) * PB + (uint32_t)((wn * 64 + j2 * 16 + l15) * 80 + lh * 16 + (ks) * 32)); \
          dst[2*j2][0] = r0; dst[2*j2][1] = r2;                                         \
          dst[2*j2+1][0] = r1; dst[2*j2+1][1] = r3; } }

#define QK_MMAS(aF, bF)                                                                 \
    { _Pragma("unroll")                                                                 \
      for (int mi = 0; mi < 2; mi++)                                                    \
          _Pragma("unroll")                                                             \
          for (int j = 0; j < 8; j++)                                                   \
              IMMA(acc[mi][j], aF[mi], bF[j][0], bF[j][1]); }

#define QK_PASS(MASK, TILEOPS, W)                                                       \
    {                                                                                   \
        _Pragma("unroll")                                                               \
        for (int i = 0; i < 2; i++)                                                     \
            _Pragma("unroll")                                                           \
            for (int j = 0; j < 8; j++)                                                 \
                _Pragma("unroll")                                                       \
                for (int r = 0; r < 4; r++) acc[i][j][r] = 0;                           \
        LOADM(0, 0, MASK);                                                              \
        LOADM(1, 1, MASK);                                                              \
        for (int t = 0; t < 16; t++) {                                                  \
            if (t + 2 < 16) { CP_WAIT(1); } else { CP_WAIT(0); }                        \
            __syncthreads();                                                            \
            if (t + 2 < 16) LOADM(t + 2, (t + 2) % 3, MASK);                            \
            const uint32_t sb_ = sbase + (uint32_t)(t % 3) * STB;                       \
            _Pragma("unroll")                                                           \
            for (int ks = 0; ks < 2; ks++) { TILEOPS }                                  \
        }                                                                               \
        _Pragma("unroll")                                                               \
        for (int i = 0; i < 2; i++)                                                     \
            _Pragma("unroll")                                                           \
            for (int j = 0; j < 8; j++)                                                 \
                _Pragma("unroll")                                                       \
                for (int r = 0; r < 4; r++) master[i][j][r] += (W) * (float)acc[i][j][r]; \
        __syncthreads();                                                                \
    }

#define P0OPS { uint32_t aF[2][4], bF[8][2]; QK_LDA(aF, 0, ks); QK_LDB(bF, 2, ks); QK_MMAS(aF, bF); }
#define P1OPS { uint32_t aF0[2][4], aF1[2][4], bF0[8][2], bF1[8][2];                    \
                QK_LDA(aF0, 0, ks); QK_LDA(aF1, 1, ks);                                 \
                QK_LDB(bF0, 2, ks); QK_LDB(bF1, 3, ks);                                 \
                QK_MMAS(aF0, bF1); QK_MMAS(aF1, bF0); }
#define P2OPS { uint32_t aF[2][4], bF[8][2]; QK_LDA(aF, 1, ks); QK_LDB(bF, 3, ks); QK_MMAS(aF, bF); }

__global__ void __launch_bounds__(256, 1)
qkv_gemm8(const signed char* __restrict__ x8,
          const signed char* __restrict__ wq8, const signed char* __restrict__ wk8,
          const signed char* __restrict__ wv8,
          __nv_bfloat16* __restrict__ Qo, __nv_bfloat16* __restrict__ Ko,
          __nv_bfloat16* __restrict__ Vo)
{
    extern __shared__ char smem[];
    const uint32_t sbase = smem_u32(smem);

    const int wsel = blockIdx.x >> 3;
    const signed char* B8 = (wsel == 0) ? wq8 : (wsel == 1) ? wk8 : wv8;
    const signed char* A0g = x8;
    const signed char* A1g = x8 + 2L * BATCH * SEQ * DIM / 2;   // plane 1
    const signed char* B0g = B8;
    const signed char* B1g = B8 + (long)DIM * DIM;

    const int tid = threadIdx.x, lid = tid & 31, wid = tid >> 5;
    const int wm = wid & 3, wn = wid >> 2;         // warp tile 32 x 64
    const int row0 = blockIdx.y * BM, col0 = (blockIdx.x & 7) * BN;
    const int l15 = lid & 15, lh = lid >> 4;

    float master[2][8][4];
    int acc[2][8][4];
    #pragma unroll
    for (int i = 0; i < 2; i++)
        #pragma unroll
        for (int j = 0; j < 8; j++)
            #pragma unroll
            for (int r = 0; r < 4; r++) master[i][j][r] = 0.f;

    auto LOADM = [&](int t, int st, int mask) {
        const long kt = (long)t * 64;
        const uint32_t sb = sbase + (uint32_t)st * STB;
        #pragma unroll
        for (int i = 0; i < 2; i++) {
            int idx = tid + i * 256;
            int row = idx >> 2, q = idx & 3;
            uint32_t so = (uint32_t)(row * 80 + q * 16);
            long ga = (long)(row0 + row) * DIM + kt + q * 16;
            long gb = (long)(col0 + row) * DIM + kt + q * 16;
            if (mask & 1) CPASYNC(sb + 0 * PB + so, A0g + ga);
            if (mask & 2) CPASYNC(sb + 1 * PB + so, A1g + ga);
            if (mask & 4) CPASYNC(sb + 2 * PB + so, B0g + gb);
            if (mask & 8) CPASYNC(sb + 3 * PB + so, B1g + gb);
        }
        CP_COMMIT();
    };

    // x = 6*(128*A0+A1)/16256 ; w = 0.1875*(128*B0+B1)/16256
    const float QK_BASE = 1.125f / (16256.f * 16256.f);
    QK_PASS(5,  P0OPS, QK_BASE * 16384.f)   // A0*B0
    QK_PASS(15, P1OPS, QK_BASE * 128.f)     // A0*B1 + A1*B0
    QK_PASS(10, P2OPS, QK_BASE)             // A1*B1

    // ---- epilogue: identical split-bf16 layouts as before ----
    const int g = lid >> 2, tig = lid & 3;
    #pragma unroll
    for (int i = 0; i < 2; i++) {
        #pragma unroll
        for (int j = 0; j < 8; j++) {
            const int c = col0 + wn * 64 + j * 8 + 2 * tig;
            #pragma unroll
            for (int s = 0; s < 2; s++) {
                const int r = row0 + wm * 32 + i * 16 + g + s * 8;
                const float v0 = master[i][j][2*s], v1 = master[i][j][2*s+1];
                if (wsel == 0) {
                    store_split_pair(reinterpret_cast<uint32_t*>(Qo + (long)r * K3P + 3L * c), v0, v1, 1);
                } else if (wsel == 1) {
                    store_split_pair(reinterpret_cast<uint32_t*>(Ko + (long)r * K3P + 3L * c), v0, v1, 2);
                } else {
                    unsigned short h0, l0, h1, l1;
                    split_us(v0, h0, l0);
                    split_us(v1, h1, l1);
                    const int bz = r >> 11, tok = r & (SEQ - 1);
                    __nv_bfloat16* Vb = Vo + (long)bz * K3S * DIM;
                    uint32_t uh = (uint32_t)h0 | ((uint32_t)h1 << 16);
                    uint32_t ul = (uint32_t)l0 | ((uint32_t)l1 << 16);
                    long rb = (long)(3 * tok) * DIM + c;
                    *reinterpret_cast<uint32_t*>(&Vb[rb])           = uh;
                    *reinterpret_cast<uint32_t*>(&Vb[rb + DIM])     = uh;
                    *reinterpret_cast<uint32_t*>(&Vb[rb + 2 * DIM]) = ul;
                }
            }
        }
    }
}

// ================= bf16 GEMM engine (scores / PV) — unchanged from R8 =================
#define LOADFRAG_NT(aoff, boff, ks, buf)                                                \
    {                                                                                   \
        _Pragma("unroll")                                                               \
        for (int mi = 0; mi < 4; mi++)                                                  \
            LDMX4(af[buf][mi][0], af[buf][mi][1], af[buf][mi][2], af[buf][mi][3],       \
                  (aoff) + (uint32_t)(((wm2 * 64 + mi * 16 + l15) * 72 + lh * 8 + (ks) * 16) * 2)); \
        _Pragma("unroll")                                                               \
        for (int j2 = 0; j2 < 4; j2++)                                                  \
            LDMX4(bf[buf][j2][0], bf[buf][j2][1], bf[buf][j2][2], bf[buf][j2][3],       \
                  (boff) + (uint32_t)(((wn2 * 64 + j2 * 16 + l15) * 72 + lh * 8 + (ks) * 16) * 2)); \
    }

#define LOADFRAG_NN(aoff, boff, ks, buf)                                                \
    {                                                                                   \
        _Pragma("unroll")                                                               \
        for (int mi = 0; mi < 4; mi++)                                                  \
            LDMX4(af[buf][mi][0], af[buf][mi][1], af[buf][mi][2], af[buf][mi][3],       \
                  (aoff) + (uint32_t)(((wm2 * 64 + mi * 16 + l15) * 72 + lh * 8 + (ks) * 16) * 2)); \
        _Pragma("unroll")                                                               \
        for (int j2 = 0; j2 < 4; j2++)                                                  \
            LDMX4T(bf[buf][j2][0], bf[buf][j2][1], bf[buf][j2][2], bf[buf][j2][3],      \
                  (boff) + (uint32_t)((((ks) * 16 + l15) * 136 + wn2 * 64 + j2 * 16 + lh * 8) * 2)); \
    }

#define COMPUTE_BODY(LOADFRAG, B0A, B0B, B1A, B1B)                                      \
    {                                                                                   \
        uint32_t af[2][4][4], bf[2][4][4];                                              \
        LOADFRAG(aoff_, boff_, 0, 0);                                                   \
        _Pragma("unroll")                                                               \
        for (int ks = 0; ks < 4; ks++) {                                                \
            const int cur = ks & 1;                                                     \
            if (ks < 3) LOADFRAG(aoff_, boff_, ks + 1, cur ^ 1);                        \
            _Pragma("unroll")                                                           \
            for (int mi = 0; mi < 4; mi++) {                                            \
                _Pragma("unroll")                                                       \
                for (int j2 = 0; j2 < 4; j2++) {                                        \
                    MMA(acc[mi][2*j2],   af[cur][mi], bf[cur][j2][B0A], bf[cur][j2][B0B]); \
                    MMA(acc[mi][2*j2+1], af[cur][mi], bf[cur][j2][B1A], bf[cur][j2][B1B]); \
                }                                                                       \
            }                                                                           \
        }                                                                               \
    }

#define COMPUTE_NT() COMPUTE_BODY(LOADFRAG_NT, 0, 2, 1, 3)
#define COMPUTE_NN() COMPUTE_BODY(LOADFRAG_NN, 0, 1, 2, 3)

#define MAINLOOP(NTtiles, LOADFN, COMPUTE_MACRO)                                        \
    LOADFN(0, 0);                                                                       \
    LOADFN(1, 1);                                                                       \
    {                                                                                   \
        int cs = 0;                                                                     \
        for (int t = 0; t < (NTtiles); t++) {                                           \
            if (t + 2 < (NTtiles)) { CP_WAIT(1); } else { CP_WAIT(0); }                 \
            __syncthreads();                                                            \
            int ldst = cs + 2; if (ldst >= 3) ldst -= 3;                                \
            if (t + 2 < (NTtiles)) LOADFN(t + 2, ldst);                                 \
            const uint32_t aoff_ = sbase + (uint32_t)cs * STAGE_BYTES;                  \
            const uint32_t boff_ = aoff_ + A_STAGE_BYTES;                               \
            COMPUTE_MACRO();                                                            \
            cs = (cs == 2) ? 0 : cs + 1;                                                \
        }                                                                               \
    }

#define ACC_DECL                                                                        \
    float acc[4][8][4];                                                                 \
    _Pragma("unroll")                                                                   \
    for (int i = 0; i < 4; i++)                                                         \
        _Pragma("unroll")                                                               \
        for (int j = 0; j < 8; j++)                                                     \
            _Pragma("unroll")                                                           \
            for (int r = 0; r < 4; r++) acc[i][j][r] = 0.f;

// ---------------- scores GEMM: triangular-packed grid ----------------
__global__ void __launch_bounds__(THREADS, 2)
scores_gemm(const __nv_bfloat16* __restrict__ Q, const __nv_bfloat16* __restrict__ Kk,
            float* __restrict__ Sc, float alpha)
{
    extern __shared__ char smem[];
    const uint32_t sbase = smem_u32(smem);

    int t_lin = blockIdx.x;
    int by = (int)((sqrtf(8.f * t_lin + 1.f) - 1.f) * 0.5f);
    while ((by + 1) * (by + 2) / 2 <= t_lin) by++;
    while (by * (by + 1) / 2 > t_lin) by--;
    const int bx = t_lin - by * (by + 1) / 2;

    const __nv_bfloat16* A = Q  + (long)blockIdx.z * SEQ * K3P;
    const __nv_bfloat16* B = Kk + (long)blockIdx.z * SEQ * K3P;
    float* C = Sc + (long)blockIdx.z * SEQ * SEQ;

    const int tid = threadIdx.x, lid = tid & 31, wid = tid >> 5;
    const int wm2 = wid & 1, wn2 = wid >> 1;
    const int row0 = by * BM, col0 = bx * BN;
    const int nT = K3P / BK;

    ACC_DECL;

    auto LOAD = [&](int t, int st) {
        const long kt = (long)t * BK;
        const uint32_t aoff = sbase + (uint32_t)st * STAGE_BYTES;
        const uint32_t boff = aoff + A_STAGE_BYTES;
        #pragma unroll
        for (int i = 0; i < 8; i++) {
            int idx = tid + i * THREADS;
            int row = idx >> 3, q = idx & 7;
            CPASYNC(aoff + (uint32_t)(row * 144 + q * 16),
                    A + (long)(row0 + row) * K3P + kt + q * 8);
            CPASYNC(boff + (uint32_t)(row * 144 + q * 16),
                    B + (long)(col0 + row) * K3P + kt + q * 8);
        }
        CP_COMMIT();
    };

    const int l15 = lid & 15, lh = lid >> 4;

    MAINLOOP(nT, LOAD, COMPUTE_NT);

    const int g = lid >> 2, tig = lid & 3;
    #pragma unroll
    for (int mi = 0; mi < 4; mi++) {
        #pragma unroll
        for (int j = 0; j < 8; j++) {
            const int c = col0 + wn2 * 64 + j * 8 + 2 * tig;
            #pragma unroll
            for (int s = 0; s < 2; s++) {
                const int r = row0 + wm2 * 64 + mi * 16 + g + s * 8;
                float2 o = make_float2(acc[mi][j][2*s] * alpha, acc[mi][j][2*s+1] * alpha);
                *reinterpret_cast<float2*>(&C[(long)r * SEQ + c]) = o;
            }
        }
    }
}

// ---------------- PV GEMM: NN, causal k-limit, longest-first ----------------
__global__ void __launch_bounds__(THREADS, 2)
pv_gemm(const __nv_bfloat16* __restrict__ P, const __nv_bfloat16* __restrict__ V,
        float* __restrict__ Out)
{
    extern __shared__ char smem[];
    const uint32_t sbase = smem_u32(smem);

    const int by = gridDim.y - 1 - blockIdx.y;
    const __nv_bfloat16* A = P + (long)blockIdx.z * SEQ * K3S;
    const __nv_bfloat16* B = V + (long)blockIdx.z * K3S * DIM;
    float* C = Out + (long)blockIdx.z * SEQ * DIM;

    const int tid = threadIdx.x, lid = tid & 31, wid = tid >> 5;
    const int wm2 = wid & 1, wn2 = wid >> 1;
    const int row0 = by * BM, col0 = blockIdx.x * BN;
    const int nT = 3 * (by + 1) * BM / BK;

    ACC_DECL;

    auto LOAD = [&](int t, int st) {
        const long kt = (long)t * BK;
        const uint32_t aoff = sbase + (uint32_t)st * STAGE_BYTES;
        const uint32_t boff = aoff + A_STAGE_BYTES;
        #pragma unroll
        for (int i = 0; i < 8; i++) {
            int idx = tid + i * THREADS;
            int row = idx >> 3, q = idx & 7;
            CPASYNC(aoff + (uint32_t)(row * 144 + q * 16),
                    A + (long)(row0 + row) * K3S + kt + q * 8);
            int kr = idx >> 4, c = (idx & 15) * 8;
            CPASYNC(boff + (uint32_t)(kr * 272 + c * 2),
                    B + (long)(kt + kr) * DIM + col0 + c);
        }
        CP_COMMIT();
    };

    const int l15 = lid & 15, lh = lid >> 4;

    MAINLOOP(nT, LOAD, COMPUTE_NN);

    const int g = lid >> 2, tig = lid & 3;
    #pragma unroll
    for (int mi = 0; mi < 4; mi++) {
        #pragma unroll
        for (int j = 0; j < 8; j++) {
            const int c = col0 + wn2 * 64 + j * 8 + 2 * tig;
            #pragma unroll
            for (int s = 0; s < 2; s++) {
                const int r = row0 + wm2 * 64 + mi * 16 + g + s * 8;
                float2 o = make_float2(acc[mi][j][2*s], acc[mi][j][2*s+1]);
                *reinterpret_cast<float2*>(&C[(long)r * DIM + c]) = o;
            }
        }
    }
}

// ---------------- softmax: fp32 scores -> split-bf16 P (A-layout) ----------------
__global__ __launch_bounds__(256)
void softmax_p2(const float* __restrict__ Sc, const int* __restrict__ mask,
                __nv_bfloat16* __restrict__ P2)
{
    __shared__ float e[SEQ];
    __shared__ float red[256];
    const int q = SEQ - 1 - blockIdx.x;
    const int b = blockIdx.y, tid = threadIdx.x;
    const float* row = Sc + ((long)b * SEQ + q) * SEQ;
    const int* mk = mask + (long)b * SEQ;
    __nv_bfloat16* pr = P2 + ((long)b * SEQ + q) * (long)K3S;
    const int qe = ((q >> 7) + 1) << 7;

    float mx = -CUDART_INF_F;
    for (int c = tid; c <= q; c += 256)
        if (mk[c]) mx = fmaxf(mx, row[c]);
    red[tid] = mx; __syncthreads();
    #pragma unroll
    for (int s = 128; s > 0; s >>= 1) {
        if (tid < s) red[tid] = fmaxf(red[tid], red[tid + s]);
        __syncthreads();
    }
    mx = red[0]; __syncthreads();

    float sum = 0.f;
    for (int c = tid; c <= q; c += 256) {
        float v = mk[c] ? __expf(row[c] - mx) : 0.f;
        e[c] = v; sum += v;
    }
    red[tid] = sum; __syncthreads();
    #pragma unroll
    for (int s = 128; s > 0; s >>= 1) {
        if (tid < s) red[tid] += red[tid + s];
        __syncthreads();
    }
    const float inv = 1.f / red[0];
    __syncthreads();

    for (int c = tid; c < qe; c += 256) {
        float v = (c <= q) ? e[c] * inv : 0.f;
        unsigned short h, l;
        split_us(v, h, l);
        pr[3*c]   = __ushort_as_bfloat16(h);
        pr[3*c+1] = __ushort_as_bfloat16(l);
        pr[3*c+2] = __ushort_as_bfloat16(h);
    }
}

// ---------------- host ----------------
extern "C" void kernel_launch(void* const* d_in, const int* in_sizes, int n_in,
                              void* d_out, int out_size)
{
    const float* x    = (const float*)d_in[0];
    const int*   mask = (const int*)  d_in[1];
    const float* Wq   = (const float*)d_in[2];
    const float* Wk   = (const float*)d_in[3];
    const float* Wv   = (const float*)d_in[4];
    float* out = (float*)d_out;

    signed char *x8p, *wq8p, *wk8p, *wv8p;
    __nv_bfloat16 *q2p, *k2p, *v2p, *p2p;
    float* sp;
    cudaGetSymbolAddress((void**)&x8p,  g_x8);
    cudaGetSymbolAddress((void**)&wq8p, g_wq8);
    cudaGetSymbolAddress((void**)&wk8p, g_wk8);
    cudaGetSymbolAddress((void**)&wv8p, g_wv8);
    cudaGetSymbolAddress((void**)&q2p,  g_Q2);
    cudaGetSymbolAddress((void**)&k2p,  g_K2);
    cudaGetSymbolAddress((void**)&v2p,  g_V2);
    cudaGetSymbolAddress((void**)&sp,   g_S);
    cudaGetSymbolAddress((void**)&p2p,  g_P2);

    static bool attr_done = false;
    if (!attr_done) {
        cudaFuncSetAttribute(qkv_gemm8,   cudaFuncAttributeMaxDynamicSharedMemorySize, QSM);
        cudaFuncSetAttribute(scores_gemm, cudaFuncAttributeMaxDynamicSharedMemorySize, SMEM_TOTAL);
        cudaFuncSetAttribute(pv_gemm,     cudaFuncAttributeMaxDynamicSharedMemorySize, SMEM_TOTAL);
        attr_done = true;
    }

    // quantize x (scale 6) and weights (scale 0.1875) into 2-slice int8
    const long nx = (long)BATCH * SEQ * DIM;
    const long nw = (long)DIM * DIM;
    quant8<<<(unsigned)((nx + 255) / 256), 256>>>(x,  x8p,  x8p  + nx, nx, 1.f / 6.f);
    quant8<<<(unsigned)((nw + 255) / 256), 256>>>(Wq, wq8p, wq8p + nw, nw, 1.f / 0.1875f);
    quant8<<<(unsigned)((nw + 255) / 256), 256>>>(Wk, wk8p, wk8p + nw, nw, 1.f / 0.1875f);
    quant8<<<(unsigned)((nw + 255) / 256), 256>>>(Wv, wv8p, wv8p + nw, nw, 1.f / 0.1875f);

    // merged QKV projections (int8 IMMA)
    dim3 gP(24, (BATCH * SEQ) / BM, 1);                  // (24, 64)
    qkv_gemm8<<<gP, 256, QSM>>>(x8p, wq8p, wk8p, wv8p, q2p, k2p, v2p);

    // scores: triangular-packed grid (bf16x3)
    dim3 gS(136, 1, BATCH);
    scores_gemm<<<gS, THREADS, SMEM_TOTAL>>>(q2p, k2p, sp, 1.f / 32.f);

    // softmax -> split P
    softmax_p2<<<dim3(SEQ, BATCH), 256>>>(sp, mask, p2p);

    // O = P @ V (bf16x3)
    dim3 gO(DIM / BN, SEQ / BM, BATCH);                  // (8, 16, 4)
    pv_gemm<<<gO, THREADS, SMEM_TOTAL>>>(p2p, v2p, out);
}

// round 10
// speedup vs baseline: 2.1487x; 2.1487x over previous
#include <cuda_runtime.h>
#include <cuda_bf16.h>
#include <math_constants.h>
#include <cstdint>

#define BATCH 4
#define SEQ   2048
#define DIM   1024
#define K3P   (3 * DIM)   // 3072
#define K3S   (3 * SEQ)   // 6144

#define BM 128
#define BN 128
#define BK 64
#define THREADS 128        // 4 warps, warp tile 64x64
#define STAGES 3
#define A_STAGE_BYTES 18432u
#define STAGE_BYTES   36864u
#define SMEM_TOTAL (STAGES * STAGE_BYTES)   // 110592 -> 2 CTA/SM

// ---------------- scratch ----------------
__device__ __nv_bfloat16 g_x2 [(long)BATCH * SEQ * K3P];
__device__ __nv_bfloat16 g_Wq2[(long)DIM * K3P];
__device__ __nv_bfloat16 g_Wk2[(long)DIM * K3P];
__device__ __nv_bfloat16 g_Wv2[(long)DIM * K3P];
__device__ __nv_bfloat16 g_Q2 [(long)BATCH * SEQ * K3P];
__device__ __nv_bfloat16 g_K2 [(long)BATCH * SEQ * K3P];
__device__ __nv_bfloat16 g_V2 [(long)BATCH * K3S * DIM];
__device__ float         g_S  [(long)BATCH * SEQ * SEQ];
__device__ __nv_bfloat16 g_P2 [(long)BATCH * SEQ * K3S];

// ---------------- asm helpers ----------------
__device__ __forceinline__ uint32_t smem_u32(const void* p) {
    uint32_t a;
    asm("{ .reg .u64 t; cvta.to.shared.u64 t, %1; cvt.u32.u64 %0, t; }" : "=r"(a) : "l"(p));
    return a;
}
#define LDMX4(r0,r1,r2,r3,addr) \
    asm volatile("ldmatrix.sync.aligned.m8n8.x4.shared.b16 {%0,%1,%2,%3}, [%4];" \
                 : "=r"(r0),"=r"(r1),"=r"(r2),"=r"(r3) : "r"(addr))
#define LDMX4T(r0,r1,r2,r3,addr) \
    asm volatile("ldmatrix.sync.aligned.m8n8.x4.trans.shared.b16 {%0,%1,%2,%3}, [%4];" \
                 : "=r"(r0),"=r"(r1),"=r"(r2),"=r"(r3) : "r"(addr))
#define MMA(c,a,b0,b1) \
    asm volatile("mma.sync.aligned.m16n8k16.row.col.f32.bf16.bf16.f32 " \
                 "{%0,%1,%2,%3}, {%4,%5,%6,%7}, {%8,%9}, {%0,%1,%2,%3};" \
                 : "+f"((c)[0]),"+f"((c)[1]),"+f"((c)[2]),"+f"((c)[3]) \
                 : "r"((a)[0]),"r"((a)[1]),"r"((a)[2]),"r"((a)[3]),"r"(b0),"r"(b1))
#define CPASYNC(s,g) \
    asm volatile("cp.async.cg.shared.global [%0], [%1], 16;" :: "r"(s),"l"(g))
#define CP_COMMIT() asm volatile("cp.async.commit_group;" ::: "memory")
#define CP_WAIT(N)  asm volatile("cp.async.wait_group %0;" :: "n"(N) : "memory")

__device__ __forceinline__ void split_us(float v, unsigned short& h, unsigned short& l) {
    __nv_bfloat16 hb = __float2bfloat16(v);
    __nv_bfloat16 lb = __float2bfloat16(v - __bfloat162float(hb));
    h = __bfloat16_as_ushort(hb);
    l = __bfloat16_as_ushort(lb);
}

__device__ __forceinline__ void store_split_pair(uint32_t* p, float v0, float v1, int lay) {
    unsigned short h0, l0, h1, l1;
    split_us(v0, h0, l0);
    split_us(v1, h1, l1);
    if (lay == 1) {        // A-layout hi,lo,hi
        p[0] = (uint32_t)h0 | ((uint32_t)l0 << 16);
        p[1] = (uint32_t)h0 | ((uint32_t)h1 << 16);
        p[2] = (uint32_t)l1 | ((uint32_t)h1 << 16);
    } else {               // B-layout hi,hi,lo
        p[0] = (uint32_t)h0 | ((uint32_t)h0 << 16);
        p[1] = (uint32_t)l0 | ((uint32_t)h1 << 16);
        p[2] = (uint32_t)h1 | ((uint32_t)l1 << 16);
    }
}

// ---------------- input conversions ----------------
__global__ void convert_x(const float4* __restrict__ in, uint2* __restrict__ out, long n4) {
    long i = (long)blockIdx.x * blockDim.x + threadIdx.x;
    if (i >= n4) return;
    float4 v = in[i];
    unsigned short h[4], l[4];
    split_us(v.x, h[0], l[0]); split_us(v.y, h[1], l[1]);
    split_us(v.z, h[2], l[2]); split_us(v.w, h[3], l[3]);
    unsigned short t[12];
    #pragma unroll
    for (int e = 0; e < 4; e++) { t[3*e] = h[e]; t[3*e+1] = l[e]; t[3*e+2] = h[e]; }
    uint2* o = out + 3 * i;
    #pragma unroll
    for (int j = 0; j < 3; j++) {
        uint2 u;
        u.x = (uint32_t)t[4*j]   | ((uint32_t)t[4*j+1] << 16);
        u.y = (uint32_t)t[4*j+2] | ((uint32_t)t[4*j+3] << 16);
        o[j] = u;
    }
}

__global__ void convert_w(const float4* __restrict__ wq, const float4* __restrict__ wk,
                          const float4* __restrict__ wv,
                          uint2* __restrict__ oq, uint2* __restrict__ ok,
                          uint2* __restrict__ ov, long n4) {
    long i = (long)blockIdx.x * blockDim.x + threadIdx.x;
    if (i >= n4) return;
    const float4* in = (blockIdx.y == 0) ? wq : (blockIdx.y == 1) ? wk : wv;
    uint2* out = (blockIdx.y == 0) ? oq : (blockIdx.y == 1) ? ok : ov;
    float4 v = in[i];
    unsigned short h[4], l[4];
    split_us(v.x, h[0], l[0]); split_us(v.y, h[1], l[1]);
    split_us(v.z, h[2], l[2]); split_us(v.w, h[3], l[3]);
    unsigned short t[12];
    #pragma unroll
    for (int e = 0; e < 4; e++) { t[3*e] = h[e]; t[3*e+1] = h[e]; t[3*e+2] = l[e]; }
    uint2* o = out + 3 * i;
    #pragma unroll
    for (int j = 0; j < 3; j++) {
        uint2 u;
        u.x = (uint32_t)t[4*j]   | ((uint32_t)t[4*j+1] << 16);
        u.y = (uint32_t)t[4*j+2] | ((uint32_t)t[4*j+3] << 16);
        o[j] = u;
    }
}

// ================= bf16 GEMM engine (4 warps, 64x64 warptile) =================
#define LOADFRAG_NT(aoff, boff, ks, buf)                                                \
    {                                                                                   \
        _Pragma("unroll")                                                               \
        for (int mi = 0; mi < 4; mi++)                                                  \
            LDMX4(af[buf][mi][0], af[buf][mi][1], af[buf][mi][2], af[buf][mi][3],       \
                  (aoff) + (uint32_t)(((wm2 * 64 + mi * 16 + l15) * 72 + lh * 8 + (ks) * 16) * 2)); \
        _Pragma("unroll")                                                               \
        for (int j2 = 0; j2 < 4; j2++)                                                  \
            LDMX4(bf[buf][j2][0], bf[buf][j2][1], bf[buf][j2][2], bf[buf][j2][3],       \
                  (boff) + (uint32_t)(((wn2 * 64 + j2 * 16 + l15) * 72 + lh * 8 + (ks) * 16) * 2)); \
    }

#define LOADFRAG_NN(aoff, boff, ks, buf)                                                \
    {                                                                                   \
        _Pragma("unroll")                                                               \
        for (int mi = 0; mi < 4; mi++)                                                  \
            LDMX4(af[buf][mi][0], af[buf][mi][1], af[buf][mi][2], af[buf][mi][3],       \
                  (aoff) + (uint32_t)(((wm2 * 64 + mi * 16 + l15) * 72 + lh * 8 + (ks) * 16) * 2)); \
        _Pragma("unroll")                                                               \
        for (int j2 = 0; j2 < 4; j2++)                                                  \
            LDMX4T(bf[buf][j2][0], bf[buf][j2][1], bf[buf][j2][2], bf[buf][j2][3],      \
                  (boff) + (uint32_t)((((ks) * 16 + l15) * 136 + wn2 * 64 + j2 * 16 + lh * 8) * 2)); \
    }

#define COMPUTE_BODY(LOADFRAG, B0A, B0B, B1A, B1B)                                      \
    {                                                                                   \
        uint32_t af[2][4][4], bf[2][4][4];                                              \
        LOADFRAG(aoff_, boff_, 0, 0);                                                   \
        _Pragma("unroll")                                                               \
        for (int ks = 0; ks < 4; ks++) {                                                \
            const int cur = ks & 1;                                                     \
            if (ks < 3) LOADFRAG(aoff_, boff_, ks + 1, cur ^ 1);                        \
            _Pragma("unroll")                                                           \
            for (int mi = 0; mi < 4; mi++) {                                            \
                _Pragma("unroll")                                                       \
                for (int j2 = 0; j2 < 4; j2++) {                                        \
                    MMA(acc[mi][2*j2],   af[cur][mi], bf[cur][j2][B0A], bf[cur][j2][B0B]); \
                    MMA(acc[mi][2*j2+1], af[cur][mi], bf[cur][j2][B1A], bf[cur][j2][B1B]); \
                }                                                                       \
            }                                                                           \
        }                                                                               \
    }

#define COMPUTE_NT() COMPUTE_BODY(LOADFRAG_NT, 0, 2, 1, 3)
#define COMPUTE_NN() COMPUTE_BODY(LOADFRAG_NN, 0, 1, 2, 3)

#define MAINLOOP(NTtiles, LOADFN, COMPUTE_MACRO)                                        \
    LOADFN(0, 0);                                                                       \
    LOADFN(1, 1);                                                                       \
    {                                                                                   \
        int cs = 0;                                                                     \
        for (int t = 0; t < (NTtiles); t++) {                                           \
            if (t + 2 < (NTtiles)) { CP_WAIT(1); } else { CP_WAIT(0); }                 \
            __syncthreads();                                                            \
            int ldst = cs + 2; if (ldst >= 3) ldst -= 3;                                \
            if (t + 2 < (NTtiles)) LOADFN(t + 2, ldst);                                 \
            const uint32_t aoff_ = sbase + (uint32_t)cs * STAGE_BYTES;                  \
            const uint32_t boff_ = aoff_ + A_STAGE_BYTES;                               \
            COMPUTE_MACRO();                                                            \
            cs = (cs == 2) ? 0 : cs + 1;                                                \
        }                                                                               \
    }

#define ACC_DECL                                                                        \
    float acc[4][8][4];                                                                 \
    _Pragma("unroll")                                                                   \
    for (int i = 0; i < 4; i++)                                                         \
        _Pragma("unroll")                                                               \
        for (int j = 0; j < 8; j++)                                                     \
            _Pragma("unroll")                                                           \
            for (int r = 0; r < 4; r++) acc[i][j][r] = 0.f;

// ---------------- projection GEMM (wsel_base: 0 => QK launch, 2 => V launch) ----------------
__global__ void __launch_bounds__(THREADS, 2)
proj_gemm(const __nv_bfloat16* __restrict__ A,
          const __nv_bfloat16* __restrict__ Wq, const __nv_bfloat16* __restrict__ Wk,
          const __nv_bfloat16* __restrict__ Wv,
          __nv_bfloat16* __restrict__ Qo, __nv_bfloat16* __restrict__ Ko,
          __nv_bfloat16* __restrict__ Vo, int wsel_base)
{
    extern __shared__ char smem[];
    const uint32_t sbase = smem_u32(smem);

    const int wsel = wsel_base + (blockIdx.x >> 3);
    const __nv_bfloat16* B = (wsel == 0) ? Wq : (wsel == 1) ? Wk : Wv;

    const int tid = threadIdx.x, lid = tid & 31, wid = tid >> 5;
    const int wm2 = wid & 1, wn2 = wid >> 1;
    const int row0 = blockIdx.y * BM, col0 = (blockIdx.x & 7) * BN;
    const int nT = K3P / BK;   // 48

    ACC_DECL;

    auto LOAD = [&](int t, int st) {
        const long kt = (long)t * BK;
        const uint32_t aoff = sbase + (uint32_t)st * STAGE_BYTES;
        const uint32_t boff = aoff + A_STAGE_BYTES;
        #pragma unroll
        for (int i = 0; i < 8; i++) {
            int idx = tid + i * THREADS;
            int row = idx >> 3, q = idx & 7;
            CPASYNC(aoff + (uint32_t)(row * 144 + q * 16),
                    A + (long)(row0 + row) * K3P + kt + q * 8);
            CPASYNC(boff + (uint32_t)(row * 144 + q * 16),
                    B + (long)(col0 + row) * K3P + kt + q * 8);
        }
        CP_COMMIT();
    };

    const int l15 = lid & 15, lh = lid >> 4;

    MAINLOOP(nT, LOAD, COMPUTE_NT);

    const int g = lid >> 2, tig = lid & 3;
    #pragma unroll
    for (int mi = 0; mi < 4; mi++) {
        #pragma unroll
        for (int j = 0; j < 8; j++) {
            const int c = col0 + wn2 * 64 + j * 8 + 2 * tig;
            #pragma unroll
            for (int s = 0; s < 2; s++) {
                const int r = row0 + wm2 * 64 + mi * 16 + g + s * 8;
                const float v0 = acc[mi][j][2*s], v1 = acc[mi][j][2*s+1];
                if (wsel == 0) {
                    store_split_pair(reinterpret_cast<uint32_t*>(Qo + (long)r * K3P + 3L * c), v0, v1, 1);
                } else if (wsel == 1) {
                    store_split_pair(reinterpret_cast<uint32_t*>(Ko + (long)r * K3P + 3L * c), v0, v1, 2);
                } else {
                    unsigned short h0, l0, h1, l1;
                    split_us(v0, h0, l0);
                    split_us(v1, h1, l1);
                    const int bz = r >> 11, tok = r & (SEQ - 1);
                    __nv_bfloat16* Vb = Vo + (long)bz * K3S * DIM;
                    uint32_t uh = (uint32_t)h0 | ((uint32_t)h1 << 16);
                    uint32_t ul = (uint32_t)l0 | ((uint32_t)l1 << 16);
                    long rb = (long)(3 * tok) * DIM + c;
                    *reinterpret_cast<uint32_t*>(&Vb[rb])           = uh;
                    *reinterpret_cast<uint32_t*>(&Vb[rb + DIM])     = uh;
                    *reinterpret_cast<uint32_t*>(&Vb[rb + 2 * DIM]) = ul;
                }
            }
        }
    }
}

// ---------------- scores GEMM: triangular-packed grid ----------------
__global__ void __launch_bounds__(THREADS, 2)
scores_gemm(const __nv_bfloat16* __restrict__ Q, const __nv_bfloat16* __restrict__ Kk,
            float* __restrict__ Sc, float alpha)
{
    extern __shared__ char smem[];
    const uint32_t sbase = smem_u32(smem);

    int t_lin = blockIdx.x;
    int by = (int)((sqrtf(8.f * t_lin + 1.f) - 1.f) * 0.5f);
    while ((by + 1) * (by + 2) / 2 <= t_lin) by++;
    while (by * (by + 1) / 2 > t_lin) by--;
    const int bx = t_lin - by * (by + 1) / 2;

    const __nv_bfloat16* A = Q  + (long)blockIdx.z * SEQ * K3P;
    const __nv_bfloat16* B = Kk + (long)blockIdx.z * SEQ * K3P;
    float* C = Sc + (long)blockIdx.z * SEQ * SEQ;

    const int tid = threadIdx.x, lid = tid & 31, wid = tid >> 5;
    const int wm2 = wid & 1, wn2 = wid >> 1;
    const int row0 = by * BM, col0 = bx * BN;
    const int nT = K3P / BK;

    ACC_DECL;

    auto LOAD = [&](int t, int st) {
        const long kt = (long)t * BK;
        const uint32_t aoff = sbase + (uint32_t)st * STAGE_BYTES;
        const uint32_t boff = aoff + A_STAGE_BYTES;
        #pragma unroll
        for (int i = 0; i < 8; i++) {
            int idx = tid + i * THREADS;
            int row = idx >> 3, q = idx & 7;
            CPASYNC(aoff + (uint32_t)(row * 144 + q * 16),
                    A + (long)(row0 + row) * K3P + kt + q * 8);
            CPASYNC(boff + (uint32_t)(row * 144 + q * 16),
                    B + (long)(col0 + row) * K3P + kt + q * 8);
        }
        CP_COMMIT();
    };

    const int l15 = lid & 15, lh = lid >> 4;

    MAINLOOP(nT, LOAD, COMPUTE_NT);

    const int g = lid >> 2, tig = lid & 3;
    #pragma unroll
    for (int mi = 0; mi < 4; mi++) {
        #pragma unroll
        for (int j = 0; j < 8; j++) {
            const int c = col0 + wn2 * 64 + j * 8 + 2 * tig;
            #pragma unroll
            for (int s = 0; s < 2; s++) {
                const int r = row0 + wm2 * 64 + mi * 16 + g + s * 8;
                float2 o = make_float2(acc[mi][j][2*s] * alpha, acc[mi][j][2*s+1] * alpha);
                *reinterpret_cast<float2*>(&C[(long)r * SEQ + c]) = o;
            }
        }
    }
}

// ---------------- PV GEMM: NN, causal k-limit, longest-first ----------------
__global__ void __launch_bounds__(THREADS, 2)
pv_gemm(const __nv_bfloat16* __restrict__ P, const __nv_bfloat16* __restrict__ V,
        float* __restrict__ Out)
{
    extern __shared__ char smem[];
    const uint32_t sbase = smem_u32(smem);

    const int by = gridDim.y - 1 - blockIdx.y;
    const __nv_bfloat16* A = P + (long)blockIdx.z * SEQ * K3S;
    const __nv_bfloat16* B = V + (long)blockIdx.z * K3S * DIM;
    float* C = Out + (long)blockIdx.z * SEQ * DIM;

    const int tid = threadIdx.x, lid = tid & 31, wid = tid >> 5;
    const int wm2 = wid & 1, wn2 = wid >> 1;
    const int row0 = by * BM, col0 = blockIdx.x * BN;
    const int nT = 3 * (by + 1) * BM / BK;

    ACC_DECL;

    auto LOAD = [&](int t, int st) {
        const long kt = (long)t * BK;
        const uint32_t aoff = sbase + (uint32_t)st * STAGE_BYTES;
        const uint32_t boff = aoff + A_STAGE_BYTES;
        #pragma unroll
        for (int i = 0; i < 8; i++) {
            int idx = tid + i * THREADS;
            int row = idx >> 3, q = idx & 7;
            CPASYNC(aoff + (uint32_t)(row * 144 + q * 16),
                    A + (long)(row0 + row) * K3S + kt + q * 8);
            int kr = idx >> 4, c = (idx & 15) * 8;
            CPASYNC(boff + (uint32_t)(kr * 272 + c * 2),
                    B + (long)(kt + kr) * DIM + col0 + c);
        }
        CP_COMMIT();
    };

    const int l15 = lid & 15, lh = lid >> 4;

    MAINLOOP(nT, LOAD, COMPUTE_NN);

    const int g = lid >> 2, tig = lid & 3;
    #pragma unroll
    for (int mi = 0; mi < 4; mi++) {
        #pragma unroll
        for (int j = 0; j < 8; j++) {
            const int c = col0 + wn2 * 64 + j * 8 + 2 * tig;
            #pragma unroll
            for (int s = 0; s < 2; s++) {
                const int r = row0 + wm2 * 64 + mi * 16 + g + s * 8;
                float2 o = make_float2(acc[mi][j][2*s], acc[mi][j][2*s+1]);
                *reinterpret_cast<float2*>(&C[(long)r * DIM + c]) = o;
            }
        }
    }
}

// ---------------- softmax: fp32 scores -> split-bf16 P, paired vector writes ----------------
__global__ __launch_bounds__(256)
void softmax_p2(const float* __restrict__ Sc, const int* __restrict__ mask,
                __nv_bfloat16* __restrict__ P2)
{
    __shared__ float e[SEQ];
    __shared__ float red[256];
    const int q = SEQ - 1 - blockIdx.x;   // longest rows first
    const int b = blockIdx.y, tid = threadIdx.x;
    const float* row = Sc + ((long)b * SEQ + q) * SEQ;
    const int* mk = mask + (long)b * SEQ;
    uint32_t* pr = reinterpret_cast<uint32_t*>(P2 + ((long)b * SEQ + q) * (long)K3S);
    const int qe = ((q >> 7) + 1) << 7;    // block-aligned end (multiple of 128)

    float mx = -CUDART_INF_F;
    for (int c = tid; c <= q; c += 256)
        if (mk[c]) mx = fmaxf(mx, row[c]);
    red[tid] = mx; __syncthreads();
    #pragma unroll
    for (int s = 128; s > 0; s >>= 1) {
        if (tid < s) red[tid] = fmaxf(red[tid], red[tid + s]);
        __syncthreads();
    }
    mx = red[0]; __syncthreads();

    float sum = 0.f;
    for (int c = tid; c <= q; c += 256) {
        float v = mk[c] ? __expf(row[c] - mx) : 0.f;
        e[c] = v; sum += v;
    }
    // zero-fill causal pad so the write phase is branch-free
    for (int c = q + 1 + tid; c < qe; c += 256) e[c] = 0.f;
    red[tid] = sum; __syncthreads();
    #pragma unroll
    for (int s = 128; s > 0; s >>= 1) {
        if (tid < s) red[tid] += red[tid + s];
        __syncthreads();
    }
    const float inv = 1.f / red[0];
    __syncthreads();

    // paired writes: 2 elements -> 3 uint32 (A-layout hi,lo,hi interleave)
    const int npair = qe >> 1;
    for (int t2 = tid; t2 < npair; t2 += 256) {
        float v0 = e[2 * t2]     * inv;
        float v1 = e[2 * t2 + 1] * inv;
        unsigned short h0, l0, h1, l1;
        split_us(v0, h0, l0);
        split_us(v1, h1, l1);
        pr[3 * t2 + 0] = (uint32_t)h0 | ((uint32_t)l0 << 16);
        pr[3 * t2 + 1] = (uint32_t)h0 | ((uint32_t)h1 << 16);
        pr[3 * t2 + 2] = (uint32_t)l1 | ((uint32_t)h1 << 16);
    }
}

// ---------------- host ----------------
extern "C" void kernel_launch(void* const* d_in, const int* in_sizes, int n_in,
                              void* d_out, int out_size)
{
    const float* x    = (const float*)d_in[0];
    const int*   mask = (const int*)  d_in[1];
    const float* Wq   = (const float*)d_in[2];
    const float* Wk   = (const float*)d_in[3];
    const float* Wv   = (const float*)d_in[4];
    float* out = (float*)d_out;

    __nv_bfloat16 *x2p, *wq2, *wk2, *wv2, *q2p, *k2p, *v2p, *p2p;
    float* sp;
    cudaGetSymbolAddress((void**)&x2p, g_x2);
    cudaGetSymbolAddress((void**)&wq2, g_Wq2);
    cudaGetSymbolAddress((void**)&wk2, g_Wk2);
    cudaGetSymbolAddress((void**)&wv2, g_Wv2);
    cudaGetSymbolAddress((void**)&q2p, g_Q2);
    cudaGetSymbolAddress((void**)&k2p, g_K2);
    cudaGetSymbolAddress((void**)&v2p, g_V2);
    cudaGetSymbolAddress((void**)&sp,  g_S);
    cudaGetSymbolAddress((void**)&p2p, g_P2);

    static cudaStream_t s2 = nullptr;
    static cudaEvent_t ev0 = nullptr, ev1 = nullptr;
    static bool init_done = false;
    if (!init_done) {
        cudaFuncSetAttribute(proj_gemm,   cudaFuncAttributeMaxDynamicSharedMemorySize, SMEM_TOTAL);
        cudaFuncSetAttribute(scores_gemm, cudaFuncAttributeMaxDynamicSharedMemorySize, SMEM_TOTAL);
        cudaFuncSetAttribute(pv_gemm,     cudaFuncAttributeMaxDynamicSharedMemorySize, SMEM_TOTAL);
        cudaStreamCreateWithFlags(&s2, cudaStreamNonBlocking);
        cudaEventCreateWithFlags(&ev0, cudaEventDisableTiming);
        cudaEventCreateWithFlags(&ev1, cudaEventDisableTiming);
        init_done = true;
    }

    const long nx4 = (long)BATCH * SEQ * DIM / 4;
    const long nw4 = (long)DIM * DIM / 4;
    convert_x<<<(unsigned)((nx4 + 255) / 256), 256>>>((const float4*)x, (uint2*)x2p, nx4);
    convert_w<<<dim3((unsigned)((nw4 + 255) / 256), 3), 256>>>(
        (const float4*)Wq, (const float4*)Wk, (const float4*)Wv,
        (uint2*)wq2, (uint2*)wk2, (uint2*)wv2, nw4);

    // fork: V projection on side stream, overlapping scores + softmax
    cudaEventRecord(ev0, 0);
    cudaStreamWaitEvent(s2, ev0, 0);
    dim3 gV(8, (BATCH * SEQ) / BM, 1);                   // wsel_base = 2 -> V
    proj_gemm<<<gV, THREADS, SMEM_TOTAL, s2>>>(x2p, wq2, wk2, wv2, q2p, k2p, v2p, 2);
    cudaEventRecord(ev1, s2);

    // main: QK projections
    dim3 gQK(16, (BATCH * SEQ) / BM, 1);                 // wsel 0 (Q), 1 (K)
    proj_gemm<<<gQK, THREADS, SMEM_TOTAL>>>(x2p, wq2, wk2, wv2, q2p, k2p, v2p, 0);

    // scores: triangular-packed grid
    dim3 gS(136, 1, BATCH);
    scores_gemm<<<gS, THREADS, SMEM_TOTAL>>>(q2p, k2p, sp, 1.f / 32.f);

    // softmax -> split P
    softmax_p2<<<dim3(SEQ, BATCH), 256>>>(sp, mask, p2p);

    // join: PV needs V
    cudaStreamWaitEvent(0, ev1, 0);
    dim3 gO(DIM / BN, SEQ / BM, BATCH);                  // (8, 16, 4)
    pv_gemm<<<gO, THREADS, SMEM_TOTAL>>>(p2p, v2p, out);
}

// round 11
// speedup vs baseline: 2.5354x; 1.1800x over previous
#include <cuda_runtime.h>
#include <cuda_bf16.h>
#include <cuda_fp16.h>
#include <math_constants.h>
#include <cstdint>

#define BATCH 4
#define SEQ   2048
#define DIM   1024
#define K3P   (3 * DIM)   // 3072: proj K (bf16 3-term)
#define K2P   (2 * DIM)   // 2048: scores K (fp16 2-term)
#define K2S   (2 * SEQ)   // 4096: PV K (fp16 2-term)

#define BM 128
#define BN 128
#define BK 64
#define THREADS 128
#define STAGES 3
#define A_STAGE_BYTES 18432u
#define STAGE_BYTES   36864u
#define SMEM_TOTAL (STAGES * STAGE_BYTES)   // 110592 -> 2 CTA/SM

// ---------------- scratch ----------------
__device__ __nv_bfloat16 g_x2 [(long)BATCH * SEQ * K3P];   // x  split bf16 A-layout
__device__ __nv_bfloat16 g_Wq2[(long)DIM * K3P];           // W  split bf16 B-layout
__device__ __nv_bfloat16 g_Wk2[(long)DIM * K3P];
__device__ __nv_bfloat16 g_Wv2[(long)DIM * K3P];
__device__ __half        g_Q2h[(long)BATCH * SEQ * K2P];   // Q fp16 (hi,lo) pairs
__device__ __half        g_K2h[(long)BATCH * SEQ * K2P];   // K fp16 (hi,hi) pairs
__device__ __half        g_V2h[(long)BATCH * K2S * DIM];   // V fp16 dup rows [2k][n]
__device__ float         g_S  [(long)BATCH * SEQ * SEQ];
__device__ __half        g_P2h[(long)BATCH * SEQ * K2S];   // P fp16 (hi,lo) pairs

// ---------------- asm helpers ----------------
__device__ __forceinline__ uint32_t smem_u32(const void* p) {
    uint32_t a;
    asm("{ .reg .u64 t; cvta.to.shared.u64 t, %1; cvt.u32.u64 %0, t; }" : "=r"(a) : "l"(p));
    return a;
}
#define LDMX4(r0,r1,r2,r3,addr) \
    asm volatile("ldmatrix.sync.aligned.m8n8.x4.shared.b16 {%0,%1,%2,%3}, [%4];" \
                 : "=r"(r0),"=r"(r1),"=r"(r2),"=r"(r3) : "r"(addr))
#define LDMX4T(r0,r1,r2,r3,addr) \
    asm volatile("ldmatrix.sync.aligned.m8n8.x4.trans.shared.b16 {%0,%1,%2,%3}, [%4];" \
                 : "=r"(r0),"=r"(r1),"=r"(r2),"=r"(r3) : "r"(addr))
#define MMA(c,a,b0,b1) \
    asm volatile("mma.sync.aligned.m16n8k16.row.col.f32.bf16.bf16.f32 " \
                 "{%0,%1,%2,%3}, {%4,%5,%6,%7}, {%8,%9}, {%0,%1,%2,%3};" \
                 : "+f"((c)[0]),"+f"((c)[1]),"+f"((c)[2]),"+f"((c)[3]) \
                 : "r"((a)[0]),"r"((a)[1]),"r"((a)[2]),"r"((a)[3]),"r"(b0),"r"(b1))
#define MMAH(c,a,b0,b1) \
    asm volatile("mma.sync.aligned.m16n8k16.row.col.f32.f16.f16.f32 " \
                 "{%0,%1,%2,%3}, {%4,%5,%6,%7}, {%8,%9}, {%0,%1,%2,%3};" \
                 : "+f"((c)[0]),"+f"((c)[1]),"+f"((c)[2]),"+f"((c)[3]) \
                 : "r"((a)[0]),"r"((a)[1]),"r"((a)[2]),"r"((a)[3]),"r"(b0),"r"(b1))
#define CPASYNC(s,g) \
    asm volatile("cp.async.cg.shared.global [%0], [%1], 16;" :: "r"(s),"l"(g))
#define CP_COMMIT() asm volatile("cp.async.commit_group;" ::: "memory")
#define CP_WAIT(N)  asm volatile("cp.async.wait_group %0;" :: "n"(N) : "memory")

__device__ __forceinline__ void split_us(float v, unsigned short& h, unsigned short& l) {
    __nv_bfloat16 hb = __float2bfloat16(v);
    __nv_bfloat16 lb = __float2bfloat16(v - __bfloat162float(hb));
    h = __bfloat16_as_ushort(hb);
    l = __bfloat16_as_ushort(lb);
}
__device__ __forceinline__ void split_h(float v, unsigned short& h, unsigned short& l) {
    __half hb = __float2half_rn(v);
    __half lb = __float2half_rn(v - __half2float(hb));
    h = __half_as_ushort(hb);
    l = __half_as_ushort(lb);
}

// ---------------- input conversions (bf16 3-term, unchanged) ----------------
__global__ void convert_x(const float4* __restrict__ in, uint2* __restrict__ out, long n4) {
    long i = (long)blockIdx.x * blockDim.x + threadIdx.x;
    if (i >= n4) return;
    float4 v = in[i];
    unsigned short h[4], l[4];
    split_us(v.x, h[0], l[0]); split_us(v.y, h[1], l[1]);
    split_us(v.z, h[2], l[2]); split_us(v.w, h[3], l[3]);
    unsigned short t[12];
    #pragma unroll
    for (int e = 0; e < 4; e++) { t[3*e] = h[e]; t[3*e+1] = l[e]; t[3*e+2] = h[e]; }
    uint2* o = out + 3 * i;
    #pragma unroll
    for (int j = 0; j < 3; j++) {
        uint2 u;
        u.x = (uint32_t)t[4*j]   | ((uint32_t)t[4*j+1] << 16);
        u.y = (uint32_t)t[4*j+2] | ((uint32_t)t[4*j+3] << 16);
        o[j] = u;
    }
}

__global__ void convert_w(const float4* __restrict__ wq, const float4* __restrict__ wk,
                          const float4* __restrict__ wv,
                          uint2* __restrict__ oq, uint2* __restrict__ ok,
                          uint2* __restrict__ ov, long n4) {
    long i = (long)blockIdx.x * blockDim.x + threadIdx.x;
    if (i >= n4) return;
    const float4* in = (blockIdx.y == 0) ? wq : (blockIdx.y == 1) ? wk : wv;
    uint2* out = (blockIdx.y == 0) ? oq : (blockIdx.y == 1) ? ok : ov;
    float4 v = in[i];
    unsigned short h[4], l[4];
    split_us(v.x, h[0], l[0]); split_us(v.y, h[1], l[1]);
    split_us(v.z, h[2], l[2]); split_us(v.w, h[3], l[3]);
    unsigned short t[12];
    #pragma unroll
    for (int e = 0; e < 4; e++) { t[3*e] = h[e]; t[3*e+1] = h[e]; t[3*e+2] = l[e]; }
    uint2* o = out + 3 * i;
    #pragma unroll
    for (int j = 0; j < 3; j++) {
        uint2 u;
        u.x = (uint32_t)t[4*j]   | ((uint32_t)t[4*j+1] << 16);
        u.y = (uint32_t)t[4*j+2] | ((uint32_t)t[4*j+3] << 16);
        o[j] = u;
    }
}

// ================= GEMM engine (4 warps, 64x64 warptile) =================
#define LOADFRAG_NT(aoff, boff, ks, buf)                                                \
    {                                                                                   \
        _Pragma("unroll")                                                               \
        for (int mi = 0; mi < 4; mi++)                                                  \
            LDMX4(af[buf][mi][0], af[buf][mi][1], af[buf][mi][2], af[buf][mi][3],       \
                  (aoff) + (uint32_t)(((wm2 * 64 + mi * 16 + l15) * 72 + lh * 8 + (ks) * 16) * 2)); \
        _Pragma("unroll")                                                               \
        for (int j2 = 0; j2 < 4; j2++)                                                  \
            LDMX4(bf[buf][j2][0], bf[buf][j2][1], bf[buf][j2][2], bf[buf][j2][3],       \
                  (boff) + (uint32_t)(((wn2 * 64 + j2 * 16 + l15) * 72 + lh * 8 + (ks) * 16) * 2)); \
    }

#define LOADFRAG_NN(aoff, boff, ks, buf)                                                \
    {                                                                                   \
        _Pragma("unroll")                                                               \
        for (int mi = 0; mi < 4; mi++)                                                  \
            LDMX4(af[buf][mi][0], af[buf][mi][1], af[buf][mi][2], af[buf][mi][3],       \
                  (aoff) + (uint32_t)(((wm2 * 64 + mi * 16 + l15) * 72 + lh * 8 + (ks) * 16) * 2)); \
        _Pragma("unroll")                                                               \
        for (int j2 = 0; j2 < 4; j2++)                                                  \
            LDMX4T(bf[buf][j2][0], bf[buf][j2][1], bf[buf][j2][2], bf[buf][j2][3],      \
                  (boff) + (uint32_t)((((ks) * 16 + l15) * 136 + wn2 * 64 + j2 * 16 + lh * 8) * 2)); \
    }

#define COMPUTE_BODY(LOADFRAG, MOP, B0A, B0B, B1A, B1B)                                 \
    {                                                                                   \
        uint32_t af[2][4][4], bf[2][4][4];                                              \
        LOADFRAG(aoff_, boff_, 0, 0);                                                   \
        _Pragma("unroll")                                                               \
        for (int ks = 0; ks < 4; ks++) {                                                \
            const int cur = ks & 1;                                                     \
            if (ks < 3) LOADFRAG(aoff_, boff_, ks + 1, cur ^ 1);                        \
            _Pragma("unroll")                                                           \
            for (int mi = 0; mi < 4; mi++) {                                            \
                _Pragma("unroll")                                                       \
                for (int j2 = 0; j2 < 4; j2++) {                                        \
                    MOP(acc[mi][2*j2],   af[cur][mi], bf[cur][j2][B0A], bf[cur][j2][B0B]); \
                    MOP(acc[mi][2*j2+1], af[cur][mi], bf[cur][j2][B1A], bf[cur][j2][B1B]); \
                }                                                                       \
            }                                                                           \
        }                                                                               \
    }

#define COMPUTE_NT()   COMPUTE_BODY(LOADFRAG_NT, MMA,  0, 2, 1, 3)
#define COMPUTE_NT_H() COMPUTE_BODY(LOADFRAG_NT, MMAH, 0, 2, 1, 3)
#define COMPUTE_NN_H() COMPUTE_BODY(LOADFRAG_NN, MMAH, 0, 1, 2, 3)

#define MAINLOOP(NTtiles, LOADFN, COMPUTE_MACRO)                                        \
    LOADFN(0, 0);                                                                       \
    LOADFN(1, 1);                                                                       \
    {                                                                                   \
        int cs = 0;                                                                     \
        for (int t = 0; t < (NTtiles); t++) {                                           \
            if (t + 2 < (NTtiles)) { CP_WAIT(1); } else { CP_WAIT(0); }                 \
            __syncthreads();                                                            \
            int ldst = cs + 2; if (ldst >= 3) ldst -= 3;                                \
            if (t + 2 < (NTtiles)) LOADFN(t + 2, ldst);                                 \
            const uint32_t aoff_ = sbase + (uint32_t)cs * STAGE_BYTES;                  \
            const uint32_t boff_ = aoff_ + A_STAGE_BYTES;                               \
            COMPUTE_MACRO();                                                            \
            cs = (cs == 2) ? 0 : cs + 1;                                                \
        }                                                                               \
    }

#define ACC_DECL                                                                        \
    float acc[4][8][4];                                                                 \
    _Pragma("unroll")                                                                   \
    for (int i = 0; i < 4; i++)                                                         \
        _Pragma("unroll")                                                               \
        for (int j = 0; j < 8; j++)                                                     \
            _Pragma("unroll")                                                           \
            for (int r = 0; r < 4; r++) acc[i][j][r] = 0.f;

// ---------------- projection GEMM (bf16 3-term; fp16 outputs) ----------------
// wsel_base: 0 => QK launch (wsel 0/1), 2 => V launch
__global__ void __launch_bounds__(THREADS, 2)
proj_gemm(const __nv_bfloat16* __restrict__ A,
          const __nv_bfloat16* __restrict__ Wq, const __nv_bfloat16* __restrict__ Wk,
          const __nv_bfloat16* __restrict__ Wv,
          __half* __restrict__ Qo, __half* __restrict__ Ko,
          __half* __restrict__ Vo, int wsel_base)
{
    extern __shared__ char smem[];
    const uint32_t sbase = smem_u32(smem);

    const int wsel = wsel_base + (blockIdx.x >> 3);
    const __nv_bfloat16* B = (wsel == 0) ? Wq : (wsel == 1) ? Wk : Wv;

    const int tid = threadIdx.x, lid = tid & 31, wid = tid >> 5;
    const int wm2 = wid & 1, wn2 = wid >> 1;
    const int row0 = blockIdx.y * BM, col0 = (blockIdx.x & 7) * BN;
    const int nT = K3P / BK;   // 48

    ACC_DECL;

    auto LOAD = [&](int t, int st) {
        const long kt = (long)t * BK;
        const uint32_t aoff = sbase + (uint32_t)st * STAGE_BYTES;
        const uint32_t boff = aoff + A_STAGE_BYTES;
        #pragma unroll
        for (int i = 0; i < 8; i++) {
            int idx = tid + i * THREADS;
            int row = idx >> 3, q = idx & 7;
            CPASYNC(aoff + (uint32_t)(row * 144 + q * 16),
                    A + (long)(row0 + row) * K3P + kt + q * 8);
            CPASYNC(boff + (uint32_t)(row * 144 + q * 16),
                    B + (long)(col0 + row) * K3P + kt + q * 8);
        }
        CP_COMMIT();
    };

    const int l15 = lid & 15, lh = lid >> 4;

    MAINLOOP(nT, LOAD, COMPUTE_NT);

    const int g = lid >> 2, tig = lid & 3;
    #pragma unroll
    for (int mi = 0; mi < 4; mi++) {
        #pragma unroll
        for (int j = 0; j < 8; j++) {
            const int c = col0 + wn2 * 64 + j * 8 + 2 * tig;
            #pragma unroll
            for (int s = 0; s < 2; s++) {
                const int r = row0 + wm2 * 64 + mi * 16 + g + s * 8;
                const float v0 = acc[mi][j][2*s], v1 = acc[mi][j][2*s+1];
                unsigned short h0, l0, h1, l1;
                split_h(v0, h0, l0);
                split_h(v1, h1, l1);
                if (wsel == 0) {        // Q: (hi,lo) pairs
                    uint32_t* p = reinterpret_cast<uint32_t*>(Qo + (long)r * K2P + 2L * c);
                    p[0] = (uint32_t)h0 | ((uint32_t)l0 << 16);
                    p[1] = (uint32_t)h1 | ((uint32_t)l1 << 16);
                } else if (wsel == 1) { // K: (hi,hi) pairs
                    uint32_t* p = reinterpret_cast<uint32_t*>(Ko + (long)r * K2P + 2L * c);
                    p[0] = (uint32_t)h0 | ((uint32_t)h0 << 16);
                    p[1] = (uint32_t)h1 | ((uint32_t)h1 << 16);
                } else {                // V: duplicated hi rows [2k][n], [2k+1][n]
                    const int bz = r >> 11, tok = r & (SEQ - 1);
                    __half* Vb = Vo + (long)bz * K2S * DIM;
                    uint32_t uh = (uint32_t)h0 | ((uint32_t)h1 << 16);
                    long rb = (long)(2 * tok) * DIM + c;
                    *reinterpret_cast<uint32_t*>(&Vb[rb])       = uh;
                    *reinterpret_cast<uint32_t*>(&Vb[rb + DIM]) = uh;
                }
            }
        }
    }
}

// ---------------- scores GEMM: fp16 2-term, triangular-packed grid ----------------
__global__ void __launch_bounds__(THREADS, 2)
scores_gemm(const __half* __restrict__ Q, const __half* __restrict__ Kk,
            float* __restrict__ Sc, float alpha)
{
    extern __shared__ char smem[];
    const uint32_t sbase = smem_u32(smem);

    int t_lin = blockIdx.x;
    int by = (int)((sqrtf(8.f * t_lin + 1.f) - 1.f) * 0.5f);
    while ((by + 1) * (by + 2) / 2 <= t_lin) by++;
    while (by * (by + 1) / 2 > t_lin) by--;
    const int bx = t_lin - by * (by + 1) / 2;

    const __half* A = Q  + (long)blockIdx.z * SEQ * K2P;
    const __half* B = Kk + (long)blockIdx.z * SEQ * K2P;
    float* C = Sc + (long)blockIdx.z * SEQ * SEQ;

    const int tid = threadIdx.x, lid = tid & 31, wid = tid >> 5;
    const int wm2 = wid & 1, wn2 = wid >> 1;
    const int row0 = by * BM, col0 = bx * BN;
    const int nT = K2P / BK;   // 32

    ACC_DECL;

    auto LOAD = [&](int t, int st) {
        const long kt = (long)t * BK;
        const uint32_t aoff = sbase + (uint32_t)st * STAGE_BYTES;
        const uint32_t boff = aoff + A_STAGE_BYTES;
        #pragma unroll
        for (int i = 0; i < 8; i++) {
            int idx = tid + i * THREADS;
            int row = idx >> 3, q = idx & 7;
            CPASYNC(aoff + (uint32_t)(row * 144 + q * 16),
                    A + (long)(row0 + row) * K2P + kt + q * 8);
            CPASYNC(boff + (uint32_t)(row * 144 + q * 16),
                    B + (long)(col0 + row) * K2P + kt + q * 8);
        }
        CP_COMMIT();
    };

    const int l15 = lid & 15, lh = lid >> 4;

    MAINLOOP(nT, LOAD, COMPUTE_NT_H);

    const int g = lid >> 2, tig = lid & 3;
    #pragma unroll
    for (int mi = 0; mi < 4; mi++) {
        #pragma unroll
        for (int j = 0; j < 8; j++) {
            const int c = col0 + wn2 * 64 + j * 8 + 2 * tig;
            #pragma unroll
            for (int s = 0; s < 2; s++) {
                const int r = row0 + wm2 * 64 + mi * 16 + g + s * 8;
                float2 o = make_float2(acc[mi][j][2*s] * alpha, acc[mi][j][2*s+1] * alpha);
                *reinterpret_cast<float2*>(&C[(long)r * SEQ + c]) = o;
            }
        }
    }
}

// ---------------- PV GEMM: fp16 2-term NN, causal k-limit, longest-first ----------------
__global__ void __launch_bounds__(THREADS, 2)
pv_gemm(const __half* __restrict__ P, const __half* __restrict__ V,
        float* __restrict__ Out)
{
    extern __shared__ char smem[];
    const uint32_t sbase = smem_u32(smem);

    const int by = gridDim.y - 1 - blockIdx.y;
    const __half* A = P + (long)blockIdx.z * SEQ * K2S;
    const __half* B = V + (long)blockIdx.z * K2S * DIM;
    float* C = Out + (long)blockIdx.z * SEQ * DIM;

    const int tid = threadIdx.x, lid = tid & 31, wid = tid >> 5;
    const int wm2 = wid & 1, wn2 = wid >> 1;
    const int row0 = by * BM, col0 = blockIdx.x * BN;
    const int nT = 2 * (by + 1) * BM / BK;   // 4*(by+1), >= 4

    ACC_DECL;

    auto LOAD = [&](int t, int st) {
        const long kt = (long)t * BK;
        const uint32_t aoff = sbase + (uint32_t)st * STAGE_BYTES;
        const uint32_t boff = aoff + A_STAGE_BYTES;
        #pragma unroll
        for (int i = 0; i < 8; i++) {
            int idx = tid + i * THREADS;
            int row = idx >> 3, q = idx & 7;
            CPASYNC(aoff + (uint32_t)(row * 144 + q * 16),
                    A + (long)(row0 + row) * K2S + kt + q * 8);
            int kr = idx >> 4, c = (idx & 15) * 8;
            CPASYNC(boff + (uint32_t)(kr * 272 + c * 2),
                    B + (long)(kt + kr) * DIM + col0 + c);
        }
        CP_COMMIT();
    };

    const int l15 = lid & 15, lh = lid >> 4;

    MAINLOOP(nT, LOAD, COMPUTE_NN_H);

    const int g = lid >> 2, tig = lid & 3;
    #pragma unroll
    for (int mi = 0; mi < 4; mi++) {
        #pragma unroll
        for (int j = 0; j < 8; j++) {
            const int c = col0 + wn2 * 64 + j * 8 + 2 * tig;
            #pragma unroll
            for (int s = 0; s < 2; s++) {
                const int r = row0 + wm2 * 64 + mi * 16 + g + s * 8;
                float2 o = make_float2(acc[mi][j][2*s], acc[mi][j][2*s+1]);
                *reinterpret_cast<float2*>(&C[(long)r * DIM + c]) = o;
            }
        }
    }
}

// ---------------- softmax: fp32 scores -> fp16 (hi,lo) P pairs ----------------
__global__ __launch_bounds__(256)
void softmax_p2(const float* __restrict__ Sc, const int* __restrict__ mask,
                __half* __restrict__ P2)
{
    __shared__ float e[SEQ];
    __shared__ float red[256];
    const int q = SEQ - 1 - blockIdx.x;   // longest rows first
    const int b = blockIdx.y, tid = threadIdx.x;
    const float* row = Sc + ((long)b * SEQ + q) * SEQ;
    const int* mk = mask + (long)b * SEQ;
    uint32_t* pr = reinterpret_cast<uint32_t*>(P2 + ((long)b * SEQ + q) * (long)K2S);
    const int qe = ((q >> 7) + 1) << 7;    // block-aligned end

    float mx = -CUDART_INF_F;
    for (int c = tid; c <= q; c += 256)
        if (mk[c]) mx = fmaxf(mx, row[c]);
    red[tid] = mx; __syncthreads();
    #pragma unroll
    for (int s = 128; s > 0; s >>= 1) {
        if (tid < s) red[tid] = fmaxf(red[tid], red[tid + s]);
        __syncthreads();
    }
    mx = red[0]; __syncthreads();

    float sum = 0.f;
    for (int c = tid; c <= q; c += 256) {
        float v = mk[c] ? __expf(row[c] - mx) : 0.f;
        e[c] = v; sum += v;
    }
    for (int c = q + 1 + tid; c < qe; c += 256) e[c] = 0.f;
    red[tid] = sum; __syncthreads();
    #pragma unroll
    for (int s = 128; s > 0; s >>= 1) {
        if (tid < s) red[tid] += red[tid + s];
        __syncthreads();
    }
    const float inv = 1.f / red[0];
    __syncthreads();

    // 2 elements -> uint2 of (hi|lo) packs
    uint2* pr2 = reinterpret_cast<uint2*>(pr);
    const int npair = qe >> 1;
    for (int t2 = tid; t2 < npair; t2 += 256) {
        float v0 = e[2 * t2]     * inv;
        float v1 = e[2 * t2 + 1] * inv;
        unsigned short h0, l0, h1, l1;
        split_h(v0, h0, l0);
        split_h(v1, h1, l1);
        uint2 u;
        u.x = (uint32_t)h0 | ((uint32_t)l0 << 16);
        u.y = (uint32_t)h1 | ((uint32_t)l1 << 16);
        pr2[t2] = u;
    }
}

// ---------------- host ----------------
extern "C" void kernel_launch(void* const* d_in, const int* in_sizes, int n_in,
                              void* d_out, int out_size)
{
    const float* x    = (const float*)d_in[0];
    const int*   mask = (const int*)  d_in[1];
    const float* Wq   = (const float*)d_in[2];
    const float* Wk   = (const float*)d_in[3];
    const float* Wv   = (const float*)d_in[4];
    float* out = (float*)d_out;

    __nv_bfloat16 *x2p, *wq2, *wk2, *wv2;
    __half *q2p, *k2p, *v2p, *p2p;
    float* sp;
    cudaGetSymbolAddress((void**)&x2p, g_x2);
    cudaGetSymbolAddress((void**)&wq2, g_Wq2);
    cudaGetSymbolAddress((void**)&wk2, g_Wk2);
    cudaGetSymbolAddress((void**)&wv2, g_Wv2);
    cudaGetSymbolAddress((void**)&q2p, g_Q2h);
    cudaGetSymbolAddress((void**)&k2p, g_K2h);
    cudaGetSymbolAddress((void**)&v2p, g_V2h);
    cudaGetSymbolAddress((void**)&sp,  g_S);
    cudaGetSymbolAddress((void**)&p2p, g_P2h);

    static cudaStream_t s2 = nullptr;
    static cudaEvent_t ev0 = nullptr, ev1 = nullptr;
    static bool init_done = false;
    if (!init_done) {
        cudaFuncSetAttribute(proj_gemm,   cudaFuncAttributeMaxDynamicSharedMemorySize, SMEM_TOTAL);
        cudaFuncSetAttribute(scores_gemm, cudaFuncAttributeMaxDynamicSharedMemorySize, SMEM_TOTAL);
        cudaFuncSetAttribute(pv_gemm,     cudaFuncAttributeMaxDynamicSharedMemorySize, SMEM_TOTAL);
        cudaStreamCreateWithFlags(&s2, cudaStreamNonBlocking);
        cudaEventCreateWithFlags(&ev0, cudaEventDisableTiming);
        cudaEventCreateWithFlags(&ev1, cudaEventDisableTiming);
        init_done = true;
    }

    const long nx4 = (long)BATCH * SEQ * DIM / 4;
    const long nw4 = (long)DIM * DIM / 4;
    convert_x<<<(unsigned)((nx4 + 255) / 256), 256>>>((const float4*)x, (uint2*)x2p, nx4);
    convert_w<<<dim3((unsigned)((nw4 + 255) / 256), 3), 256>>>(
        (const float4*)Wq, (const float4*)Wk, (const float4*)Wv,
        (uint2*)wq2, (uint2*)wk2, (uint2*)wv2, nw4);

    // fork: V projection on side stream, overlapping scores + softmax
    cudaEventRecord(ev0, 0);
    cudaStreamWaitEvent(s2, ev0, 0);
    dim3 gV(8, (BATCH * SEQ) / BM, 1);
    proj_gemm<<<gV, THREADS, SMEM_TOTAL, s2>>>(x2p, wq2, wk2, wv2, q2p, k2p, v2p, 2);
    cudaEventRecord(ev1, s2);

    // main: QK projections
    dim3 gQK(16, (BATCH * SEQ) / BM, 1);
    proj_gemm<<<gQK, THREADS, SMEM_TOTAL>>>(x2p, wq2, wk2, wv2, q2p, k2p, v2p, 0);

    // scores: fp16 2-term, triangular-packed grid
    dim3 gS(136, 1, BATCH);
    scores_gemm<<<gS, THREADS, SMEM_TOTAL>>>(q2p, k2p, sp, 1.f / 32.f);

    // softmax -> fp16 (hi,lo) P
    softmax_p2<<<dim3(SEQ, BATCH), 256>>>(sp, mask, p2p);

    // join: PV needs V
    cudaStreamWaitEvent(0, ev1, 0);
    dim3 gO(DIM / BN, SEQ / BM, BATCH);
    pv_gemm<<<gO, THREADS, SMEM_TOTAL>>>(p2p, v2p, out);
}

// round 12
// speedup vs baseline: 3.1715x; 1.2509x over previous
#include <cuda_runtime.h>
#include <cuda_bf16.h>
#include <cuda_fp16.h>
#include <math_constants.h>
#include <cstdint>

#define BATCH 4
#define SEQ   2048
#define DIM   1024
#define K2P   (2 * DIM)   // 2048: fp16 2-term K for proj & scores
#define K2S   (2 * SEQ)   // 4096: fp16 2-term K for PV

#define BM 128
#define BN 128
#define BK 64
#define THREADS 128
#define STAGES 3
#define A_STAGE_BYTES 18432u
#define STAGE_BYTES   36864u
#define SMEM_TOTAL (STAGES * STAGE_BYTES)   // 110592 -> 2 CTA/SM

// ---------------- scratch ----------------
__device__ __half g_x2h[(long)BATCH * SEQ * K2P];   // x  fp16 (hi,lo) pairs
__device__ __half g_Wq2[(long)DIM * K2P];           // W  fp16 (hi,hi) pairs
__device__ __half g_Wk2[(long)DIM * K2P];
__device__ __half g_Wv2[(long)DIM * K2P];
__device__ __half g_Q2h[(long)BATCH * SEQ * K2P];   // Q fp16 (hi,lo) pairs
__device__ __half g_K2h[(long)BATCH * SEQ * K2P];   // K fp16 (hi,hi) pairs
__device__ __half g_V2h[(long)BATCH * K2S * DIM];   // V fp16 dup rows [2k][n]
__device__ float  g_S  [(long)BATCH * SEQ * SEQ];
__device__ __half g_P2h[(long)BATCH * SEQ * K2S];   // P fp16 (hi,lo) pairs

// ---------------- asm helpers ----------------
__device__ __forceinline__ uint32_t smem_u32(const void* p) {
    uint32_t a;
    asm("{ .reg .u64 t; cvta.to.shared.u64 t, %1; cvt.u32.u64 %0, t; }" : "=r"(a) : "l"(p));
    return a;
}
#define LDMX4(r0,r1,r2,r3,addr) \
    asm volatile("ldmatrix.sync.aligned.m8n8.x4.shared.b16 {%0,%1,%2,%3}, [%4];" \
                 : "=r"(r0),"=r"(r1),"=r"(r2),"=r"(r3) : "r"(addr))
#define LDMX4T(r0,r1,r2,r3,addr) \
    asm volatile("ldmatrix.sync.aligned.m8n8.x4.trans.shared.b16 {%0,%1,%2,%3}, [%4];" \
                 : "=r"(r0),"=r"(r1),"=r"(r2),"=r"(r3) : "r"(addr))
#define MMAH(c,a,b0,b1) \
    asm volatile("mma.sync.aligned.m16n8k16.row.col.f32.f16.f16.f32 " \
                 "{%0,%1,%2,%3}, {%4,%5,%6,%7}, {%8,%9}, {%0,%1,%2,%3};" \
                 : "+f"((c)[0]),"+f"((c)[1]),"+f"((c)[2]),"+f"((c)[3]) \
                 : "r"((a)[0]),"r"((a)[1]),"r"((a)[2]),"r"((a)[3]),"r"(b0),"r"(b1))
#define CPASYNC(s,g) \
    asm volatile("cp.async.cg.shared.global [%0], [%1], 16;" :: "r"(s),"l"(g))
#define CP_COMMIT() asm volatile("cp.async.commit_group;" ::: "memory")
#define CP_WAIT(N)  asm volatile("cp.async.wait_group %0;" :: "n"(N) : "memory")

__device__ __forceinline__ void split_h(float v, unsigned short& h, unsigned short& l) {
    __half hb = __float2half_rn(v);
    __half lb = __float2half_rn(v - __half2float(hb));
    h = __half_as_ushort(hb);
    l = __half_as_ushort(lb);
}

// ---------------- input conversions (fp16 2-term) ----------------
// x: (hi,lo) pairs
__global__ void convert_x(const float4* __restrict__ in, uint2* __restrict__ out, long n4) {
    long i = (long)blockIdx.x * blockDim.x + threadIdx.x;
    if (i >= n4) return;
    float4 v = in[i];
    unsigned short h[4], l[4];
    split_h(v.x, h[0], l[0]); split_h(v.y, h[1], l[1]);
    split_h(v.z, h[2], l[2]); split_h(v.w, h[3], l[3]);
    uint2* o = out + 2 * i;
    uint2 u0, u1;
    u0.x = (uint32_t)h[0] | ((uint32_t)l[0] << 16);
    u0.y = (uint32_t)h[1] | ((uint32_t)l[1] << 16);
    u1.x = (uint32_t)h[2] | ((uint32_t)l[2] << 16);
    u1.y = (uint32_t)h[3] | ((uint32_t)l[3] << 16);
    o[0] = u0; o[1] = u1;
}

// W (all 3 in one launch): (hi,hi) pairs
__global__ void convert_w(const float4* __restrict__ wq, const float4* __restrict__ wk,
                          const float4* __restrict__ wv,
                          uint2* __restrict__ oq, uint2* __restrict__ ok,
                          uint2* __restrict__ ov, long n4) {
    long i = (long)blockIdx.x * blockDim.x + threadIdx.x;
    if (i >= n4) return;
    const float4* in = (blockIdx.y == 0) ? wq : (blockIdx.y == 1) ? wk : wv;
    uint2* out = (blockIdx.y == 0) ? oq : (blockIdx.y == 1) ? ok : ov;
    float4 v = in[i];
    unsigned short h[4];
    h[0] = __half_as_ushort(__float2half_rn(v.x));
    h[1] = __half_as_ushort(__float2half_rn(v.y));
    h[2] = __half_as_ushort(__float2half_rn(v.z));
    h[3] = __half_as_ushort(__float2half_rn(v.w));
    uint2* o = out + 2 * i;
    uint2 u0, u1;
    u0.x = (uint32_t)h[0] | ((uint32_t)h[0] << 16);
    u0.y = (uint32_t)h[1] | ((uint32_t)h[1] << 16);
    u1.x = (uint32_t)h[2] | ((uint32_t)h[2] << 16);
    u1.y = (uint32_t)h[3] | ((uint32_t)h[3] << 16);
    o[0] = u0; o[1] = u1;
}

// ================= GEMM engine (4 warps, 64x64 warptile) =================
#define LOADFRAG_NT(aoff, boff, ks, buf)                                                \
    {                                                                                   \
        _Pragma("unroll")                                                               \
        for (int mi = 0; mi < 4; mi++)                                                  \
            LDMX4(af[buf][mi][0], af[buf][mi][1], af[buf][mi][2], af[buf][mi][3],       \
                  (aoff) + (uint32_t)(((wm2 * 64 + mi * 16 + l15) * 72 + lh * 8 + (ks) * 16) * 2)); \
        _Pragma("unroll")                                                               \
        for (int j2 = 0; j2 < 4; j2++)                                                  \
            LDMX4(bf[buf][j2][0], bf[buf][j2][1], bf[buf][j2][2], bf[buf][j2][3],       \
                  (boff) + (uint32_t)(((wn2 * 64 + j2 * 16 + l15) * 72 + lh * 8 + (ks) * 16) * 2)); \
    }

#define LOADFRAG_NN(aoff, boff, ks, buf)                                                \
    {                                                                                   \
        _Pragma("unroll")                                                               \
        for (int mi = 0; mi < 4; mi++)                                                  \
            LDMX4(af[buf][mi][0], af[buf][mi][1], af[buf][mi][2], af[buf][mi][3],       \
                  (aoff) + (uint32_t)(((wm2 * 64 + mi * 16 + l15) * 72 + lh * 8 + (ks) * 16) * 2)); \
        _Pragma("unroll")                                                               \
        for (int j2 = 0; j2 < 4; j2++)                                                  \
            LDMX4T(bf[buf][j2][0], bf[buf][j2][1], bf[buf][j2][2], bf[buf][j2][3],      \
                  (boff) + (uint32_t)((((ks) * 16 + l15) * 136 + wn2 * 64 + j2 * 16 + lh * 8) * 2)); \
    }

#define COMPUTE_BODY(LOADFRAG, MOP, B0A, B0B, B1A, B1B)                                 \
    {                                                                                   \
        uint32_t af[2][4][4], bf[2][4][4];                                              \
        LOADFRAG(aoff_, boff_, 0, 0);                                                   \
        _Pragma("unroll")                                                               \
        for (int ks = 0; ks < 4; ks++) {                                                \
            const int cur = ks & 1;                                                     \
            if (ks < 3) LOADFRAG(aoff_, boff_, ks + 1, cur ^ 1);                        \
            _Pragma("unroll")                                                           \
            for (int mi = 0; mi < 4; mi++) {                                            \
                _Pragma("unroll")                                                       \
                for (int j2 = 0; j2 < 4; j2++) {                                        \
                    MOP(acc[mi][2*j2],   af[cur][mi], bf[cur][j2][B0A], bf[cur][j2][B0B]); \
                    MOP(acc[mi][2*j2+1], af[cur][mi], bf[cur][j2][B1A], bf[cur][j2][B1B]); \
                }                                                                       \
            }                                                                           \
        }                                                                               \
    }

#define COMPUTE_NT_H() COMPUTE_BODY(LOADFRAG_NT, MMAH, 0, 2, 1, 3)
#define COMPUTE_NN_H() COMPUTE_BODY(LOADFRAG_NN, MMAH, 0, 1, 2, 3)

#define MAINLOOP(NTtiles, LOADFN, COMPUTE_MACRO)                                        \
    LOADFN(0, 0);                                                                       \
    LOADFN(1, 1);                                                                       \
    {                                                                                   \
        int cs = 0;                                                                     \
        for (int t = 0; t < (NTtiles); t++) {                                           \
            if (t + 2 < (NTtiles)) { CP_WAIT(1); } else { CP_WAIT(0); }                 \
            __syncthreads();                                                            \
            int ldst = cs + 2; if (ldst >= 3) ldst -= 3;                                \
            if (t + 2 < (NTtiles)) LOADFN(t + 2, ldst);                                 \
            const uint32_t aoff_ = sbase + (uint32_t)cs * STAGE_BYTES;                  \
            const uint32_t boff_ = aoff_ + A_STAGE_BYTES;                               \
            COMPUTE_MACRO();                                                            \
            cs = (cs == 2) ? 0 : cs + 1;                                                \
        }                                                                               \
    }

#define ACC_DECL                                                                        \
    float acc[4][8][4];                                                                 \
    _Pragma("unroll")                                                                   \
    for (int i = 0; i < 4; i++)                                                         \
        _Pragma("unroll")                                                               \
        for (int j = 0; j < 8; j++)                                                     \
            _Pragma("unroll")                                                           \
            for (int r = 0; r < 4; r++) acc[i][j][r] = 0.f;

// ---------------- projection GEMM (fp16 2-term; fp16 outputs) ----------------
// wsel_base: 0 => QK launch (wsel 0/1), 2 => V launch
__global__ void __launch_bounds__(THREADS, 2)
proj_gemm(const __half* __restrict__ A,
          const __half* __restrict__ Wq, const __half* __restrict__ Wk,
          const __half* __restrict__ Wv,
          __half* __restrict__ Qo, __half* __restrict__ Ko,
          __half* __restrict__ Vo, int wsel_base)
{
    extern __shared__ char smem[];
    const uint32_t sbase = smem_u32(smem);

    const int wsel = wsel_base + (blockIdx.x >> 3);
    const __half* B = (wsel == 0) ? Wq : (wsel == 1) ? Wk : Wv;

    const int tid = threadIdx.x, lid = tid & 31, wid = tid >> 5;
    const int wm2 = wid & 1, wn2 = wid >> 1;
    const int row0 = blockIdx.y * BM, col0 = (blockIdx.x & 7) * BN;
    const int nT = K2P / BK;   // 32

    ACC_DECL;

    auto LOAD = [&](int t, int st) {
        const long kt = (long)t * BK;
        const uint32_t aoff = sbase + (uint32_t)st * STAGE_BYTES;
        const uint32_t boff = aoff + A_STAGE_BYTES;
        #pragma unroll
        for (int i = 0; i < 8; i++) {
            int idx = tid + i * THREADS;
            int row = idx >> 3, q = idx & 7;
            CPASYNC(aoff + (uint32_t)(row * 144 + q * 16),
                    A + (long)(row0 + row) * K2P + kt + q * 8);
            CPASYNC(boff + (uint32_t)(row * 144 + q * 16),
                    B + (long)(col0 + row) * K2P + kt + q * 8);
        }
        CP_COMMIT();
    };

    const int l15 = lid & 15, lh = lid >> 4;

    MAINLOOP(nT, LOAD, COMPUTE_NT_H);

    const int g = lid >> 2, tig = lid & 3;
    #pragma unroll
    for (int mi = 0; mi < 4; mi++) {
        #pragma unroll
        for (int j = 0; j < 8; j++) {
            const int c = col0 + wn2 * 64 + j * 8 + 2 * tig;
            #pragma unroll
            for (int s = 0; s < 2; s++) {
                const int r = row0 + wm2 * 64 + mi * 16 + g + s * 8;
                const float v0 = acc[mi][j][2*s], v1 = acc[mi][j][2*s+1];
                unsigned short h0, l0, h1, l1;
                split_h(v0, h0, l0);
                split_h(v1, h1, l1);
                if (wsel == 0) {        // Q: (hi,lo) pairs
                    uint32_t* p = reinterpret_cast<uint32_t*>(Qo + (long)r * K2P + 2L * c);
                    p[0] = (uint32_t)h0 | ((uint32_t)l0 << 16);
                    p[1] = (uint32_t)h1 | ((uint32_t)l1 << 16);
                } else if (wsel == 1) { // K: (hi,hi) pairs
                    uint32_t* p = reinterpret_cast<uint32_t*>(Ko + (long)r * K2P + 2L * c);
                    p[0] = (uint32_t)h0 | ((uint32_t)h0 << 16);
                    p[1] = (uint32_t)h1 | ((uint32_t)h1 << 16);
                } else {                // V: duplicated hi rows [2k][n], [2k+1][n]
                    const int bz = r >> 11, tok = r & (SEQ - 1);
                    __half* Vb = Vo + (long)bz * K2S * DIM;
                    uint32_t uh = (uint32_t)h0 | ((uint32_t)h1 << 16);
                    long rb = (long)(2 * tok) * DIM + c;
                    *reinterpret_cast<uint32_t*>(&Vb[rb])       = uh;
                    *reinterpret_cast<uint32_t*>(&Vb[rb + DIM]) = uh;
                }
            }
        }
    }
}

// ---------------- scores GEMM: fp16 2-term, triangular-packed grid ----------------
__global__ void __launch_bounds__(THREADS, 2)
scores_gemm(const __half* __restrict__ Q, const __half* __restrict__ Kk,
            float* __restrict__ Sc, float alpha)
{
    extern __shared__ char smem[];
    const uint32_t sbase = smem_u32(smem);

    int t_lin = blockIdx.x;
    int by = (int)((sqrtf(8.f * t_lin + 1.f) - 1.f) * 0.5f);
    while ((by + 1) * (by + 2) / 2 <= t_lin) by++;
    while (by * (by + 1) / 2 > t_lin) by--;
    const int bx = t_lin - by * (by + 1) / 2;

    const __half* A = Q  + (long)blockIdx.z * SEQ * K2P;
    const __half* B = Kk + (long)blockIdx.z * SEQ * K2P;
    float* C = Sc + (long)blockIdx.z * SEQ * SEQ;

    const int tid = threadIdx.x, lid = tid & 31, wid = tid >> 5;
    const int wm2 = wid & 1, wn2 = wid >> 1;
    const int row0 = by * BM, col0 = bx * BN;
    const int nT = K2P / BK;   // 32

    ACC_DECL;

    auto LOAD = [&](int t, int st) {
        const long kt = (long)t * BK;
        const uint32_t aoff = sbase + (uint32_t)st * STAGE_BYTES;
        const uint32_t boff = aoff + A_STAGE_BYTES;
        #pragma unroll
        for (int i = 0; i < 8; i++) {
            int idx = tid + i * THREADS;
            int row = idx >> 3, q = idx & 7;
            CPASYNC(aoff + (uint32_t)(row * 144 + q * 16),
                    A + (long)(row0 + row) * K2P + kt + q * 8);
            CPASYNC(boff + (uint32_t)(row * 144 + q * 16),
                    B + (long)(col0 + row) * K2P + kt + q * 8);
        }
        CP_COMMIT();
    };

    const int l15 = lid & 15, lh = lid >> 4;

    MAINLOOP(nT, LOAD, COMPUTE_NT_H);

    const int g = lid >> 2, tig = lid & 3;
    #pragma unroll
    for (int mi = 0; mi < 4; mi++) {
        #pragma unroll
        for (int j = 0; j < 8; j++) {
            const int c = col0 + wn2 * 64 + j * 8 + 2 * tig;
            #pragma unroll
            for (int s = 0; s < 2; s++) {
                const int r = row0 + wm2 * 64 + mi * 16 + g + s * 8;
                float2 o = make_float2(acc[mi][j][2*s] * alpha, acc[mi][j][2*s+1] * alpha);
                *reinterpret_cast<float2*>(&C[(long)r * SEQ + c]) = o;
            }
        }
    }
}

// ---------------- PV GEMM: fp16 2-term NN, causal k-limit, longest-first ----------------
__global__ void __launch_bounds__(THREADS, 2)
pv_gemm(const __half* __restrict__ P, const __half* __restrict__ V,
        float* __restrict__ Out)
{
    extern __shared__ char smem[];
    const uint32_t sbase = smem_u32(smem);

    const int by = gridDim.y - 1 - blockIdx.y;
    const __half* A = P + (long)blockIdx.z * SEQ * K2S;
    const __half* B = V + (long)blockIdx.z * K2S * DIM;
    float* C = Out + (long)blockIdx.z * SEQ * DIM;

    const int tid = threadIdx.x, lid = tid & 31, wid = tid >> 5;
    const int wm2 = wid & 1, wn2 = wid >> 1;
    const int row0 = by * BM, col0 = blockIdx.x * BN;
    const int nT = 2 * (by + 1) * BM / BK;   // 4*(by+1), >= 4

    ACC_DECL;

    auto LOAD = [&](int t, int st) {
        const long kt = (long)t * BK;
        const uint32_t aoff = sbase + (uint32_t)st * STAGE_BYTES;
        const uint32_t boff = aoff + A_STAGE_BYTES;
        #pragma unroll
        for (int i = 0; i < 8; i++) {
            int idx = tid + i * THREADS;
            int row = idx >> 3, q = idx & 7;
            CPASYNC(aoff + (uint32_t)(row * 144 + q * 16),
                    A + (long)(row0 + row) * K2S + kt + q * 8);
            int kr = idx >> 4, c = (idx & 15) * 8;
            CPASYNC(boff + (uint32_t)(kr * 272 + c * 2),
                    B + (long)(kt + kr) * DIM + col0 + c);
        }
        CP_COMMIT();
    };

    const int l15 = lid & 15, lh = lid >> 4;

    MAINLOOP(nT, LOAD, COMPUTE_NN_H);

    const int g = lid >> 2, tig = lid & 3;
    #pragma unroll
    for (int mi = 0; mi < 4; mi++) {
        #pragma unroll
        for (int j = 0; j < 8; j++) {
            const int c = col0 + wn2 * 64 + j * 8 + 2 * tig;
            #pragma unroll
            for (int s = 0; s < 2; s++) {
                const int r = row0 + wm2 * 64 + mi * 16 + g + s * 8;
                float2 o = make_float2(acc[mi][j][2*s], acc[mi][j][2*s+1]);
                *reinterpret_cast<float2*>(&C[(long)r * DIM + c]) = o;
            }
        }
    }
}

// ---------------- softmax: fp32 scores -> fp16 (hi,lo) P pairs ----------------
__global__ __launch_bounds__(256)
void softmax_p2(const float* __restrict__ Sc, const int* __restrict__ mask,
                __half* __restrict__ P2)
{
    __shared__ float e[SEQ];
    __shared__ float red[256];
    const int q = SEQ - 1 - blockIdx.x;   // longest rows first
    const int b = blockIdx.y, tid = threadIdx.x;
    const float* row = Sc + ((long)b * SEQ + q) * SEQ;
    const int* mk = mask + (long)b * SEQ;
    uint2* pr2 = reinterpret_cast<uint2*>(P2 + ((long)b * SEQ + q) * (long)K2S);
    const int qe = ((q >> 7) + 1) << 7;    // block-aligned end

    float mx = -CUDART_INF_F;
    for (int c = tid; c <= q; c += 256)
        if (mk[c]) mx = fmaxf(mx, row[c]);
    red[tid] = mx; __syncthreads();
    #pragma unroll
    for (int s = 128; s > 0; s >>= 1) {
        if (tid < s) red[tid] = fmaxf(red[tid], red[tid + s]);
        __syncthreads();
    }
    mx = red[0]; __syncthreads();

    float sum = 0.f;
    for (int c = tid; c <= q; c += 256) {
        float v = mk[c] ? __expf(row[c] - mx) : 0.f;
        e[c] = v; sum += v;
    }
    for (int c = q + 1 + tid; c < qe; c += 256) e[c] = 0.f;
    red[tid] = sum; __syncthreads();
    #pragma unroll
    for (int s = 128; s > 0; s >>= 1) {
        if (tid < s) red[tid] += red[tid + s];
        __syncthreads();
    }
    const float inv = 1.f / red[0];
    __syncthreads();

    const int npair = qe >> 1;
    for (int t2 = tid; t2 < npair; t2 += 256) {
        float v0 = e[2 * t2]     * inv;
        float v1 = e[2 * t2 + 1] * inv;
        unsigned short h0, l0, h1, l1;
        split_h(v0, h0, l0);
        split_h(v1, h1, l1);
        uint2 u;
        u.x = (uint32_t)h0 | ((uint32_t)l0 << 16);
        u.y = (uint32_t)h1 | ((uint32_t)l1 << 16);
        pr2[t2] = u;
    }
}

// ---------------- host ----------------
extern "C" void kernel_launch(void* const* d_in, const int* in_sizes, int n_in,
                              void* d_out, int out_size)
{
    const float* x    = (const float*)d_in[0];
    const int*   mask = (const int*)  d_in[1];
    const float* Wq   = (const float*)d_in[2];
    const float* Wk   = (const float*)d_in[3];
    const float* Wv   = (const float*)d_in[4];
    float* out = (float*)d_out;

    __half *x2p, *wq2, *wk2, *wv2, *q2p, *k2p, *v2p, *p2p;
    float* sp;
    cudaGetSymbolAddress((void**)&x2p, g_x2h);
    cudaGetSymbolAddress((void**)&wq2, g_Wq2);
    cudaGetSymbolAddress((void**)&wk2, g_Wk2);
    cudaGetSymbolAddress((void**)&wv2, g_Wv2);
    cudaGetSymbolAddress((void**)&q2p, g_Q2h);
    cudaGetSymbolAddress((void**)&k2p, g_K2h);
    cudaGetSymbolAddress((void**)&v2p, g_V2h);
    cudaGetSymbolAddress((void**)&sp,  g_S);
    cudaGetSymbolAddress((void**)&p2p, g_P2h);

    static cudaStream_t s2 = nullptr;
    static cudaEvent_t ev0 = nullptr, ev1 = nullptr;
    static bool init_done = false;
    if (!init_done) {
        cudaFuncSetAttribute(proj_gemm,   cudaFuncAttributeMaxDynamicSharedMemorySize, SMEM_TOTAL);
        cudaFuncSetAttribute(scores_gemm, cudaFuncAttributeMaxDynamicSharedMemorySize, SMEM_TOTAL);
        cudaFuncSetAttribute(pv_gemm,     cudaFuncAttributeMaxDynamicSharedMemorySize, SMEM_TOTAL);
        cudaStreamCreateWithFlags(&s2, cudaStreamNonBlocking);
        cudaEventCreateWithFlags(&ev0, cudaEventDisableTiming);
        cudaEventCreateWithFlags(&ev1, cudaEventDisableTiming);
        init_done = true;
    }

    const long nx4 = (long)BATCH * SEQ * DIM / 4;
    const long nw4 = (long)DIM * DIM / 4;
    convert_x<<<(unsigned)((nx4 + 255) / 256), 256>>>((const float4*)x, (uint2*)x2p, nx4);
    convert_w<<<dim3((unsigned)((nw4 + 255) / 256), 3), 256>>>(
        (const float4*)Wq, (const float4*)Wk, (const float4*)Wv,
        (uint2*)wq2, (uint2*)wk2, (uint2*)wv2, nw4);

    // fork: V projection on side stream, overlapping scores + softmax
    cudaEventRecord(ev0, 0);
    cudaStreamWaitEvent(s2, ev0, 0);
    dim3 gV(8, (BATCH * SEQ) / BM, 1);
    proj_gemm<<<gV, THREADS, SMEM_TOTAL, s2>>>(x2p, wq2, wk2, wv2, q2p, k2p, v2p, 2);
    cudaEventRecord(ev1, s2);

    // main: QK projections
    dim3 gQK(16, (BATCH * SEQ) / BM, 1);
    proj_gemm<<<gQK, THREADS, SMEM_TOTAL>>>(x2p, wq2, wk2, wv2, q2p, k2p, v2p, 0);

    // scores: fp16 2-term, triangular-packed grid
    dim3 gS(136, 1, BATCH);
    scores_gemm<<<gS, THREADS, SMEM_TOTAL>>>(q2p, k2p, sp, 1.f / 32.f);

    // softmax -> fp16 (hi,lo) P
    softmax_p2<<<dim3(SEQ, BATCH), 256>>>(sp, mask, p2p);

    // join: PV needs V
    cudaStreamWaitEvent(0, ev1, 0);
    dim3 gO(DIM / BN, SEQ / BM, BATCH);
    pv_gemm<<<gO, THREADS, SMEM_TOTAL>>>(p2p, v2p, out);
}